// round 9
// baseline (speedup 1.0000x reference)
#include <cuda_runtime.h>
#include <cuda_bf16.h>
#include <cstdint>

// ---------------------------------------------------------------------------
// Focus-DETR encoder — round 9: gemm_ln widened to 512 threads (16 warps,
// 16 cols/warp), same tiling/L2 traffic. Everything else as round 8.
// ---------------------------------------------------------------------------

#define L_LAYERS 6
#define Bn 4
#define NN 23890
#define Kn 1024
#define Dn 256
#define Hn 8
#define HDn 32
#define FFNn 1024
#define NCLSn 15

#define ROWS (Bn * Kn)          // 4096
#define RD   (ROWS * Dn)        // 1048576 elements

// ---------------- scratch carving ----------------
constexpr size_t SZ_F  = (size_t)RD * 4;
constexpr size_t SZ_B  = (size_t)RD * 2;
constexpr size_t SZ_H  = (size_t)ROWS * FFNn * 2;
constexpr size_t SZ_WD = (size_t)L_LAYERS * Dn * Dn * 2;
constexpr size_t SZ_W1 = (size_t)L_LAYERS * Dn * FFNn * 2;

constexpr size_t OF_TGT = 0;
constexpr size_t OF_XB  = OF_TGT + SZ_F;
constexpr size_t OF_QKH = OF_XB  + SZ_F;
constexpr size_t OF_QKL = OF_QKH + SZ_B;
constexpr size_t OF_TGH = OF_QKL + SZ_B;
constexpr size_t OF_TGL = OF_TGH + SZ_B;
constexpr size_t OF_QH  = OF_TGL + SZ_B;
constexpr size_t OF_QL  = OF_QH  + SZ_B;
constexpr size_t OF_KH  = OF_QL  + SZ_B;
constexpr size_t OF_KL  = OF_KH  + SZ_B;
constexpr size_t OF_VH  = OF_KL  + SZ_B;
constexpr size_t OF_VL  = OF_VH  + SZ_B;
constexpr size_t OF_ATH = OF_VL  + SZ_B;
constexpr size_t OF_ATL = OF_ATH + SZ_B;
constexpr size_t OF_XH  = OF_ATL + SZ_B;
constexpr size_t OF_XL  = OF_XH  + SZ_B;
constexpr size_t OF_HH  = OF_XL  + SZ_B;
constexpr size_t OF_HL  = OF_HH  + SZ_H;
constexpr size_t OF_WQH = OF_HL  + SZ_H;
constexpr size_t OF_WQL = OF_WQH + SZ_WD;
constexpr size_t OF_WKH = OF_WQL + SZ_WD;
constexpr size_t OF_WKL = OF_WKH + SZ_WD;
constexpr size_t OF_WVH = OF_WKL + SZ_WD;
constexpr size_t OF_WVL = OF_WVH + SZ_WD;
constexpr size_t OF_WOH = OF_WVL + SZ_WD;
constexpr size_t OF_WOL = OF_WOH + SZ_WD;
constexpr size_t OF_W1H = OF_WOL + SZ_WD;
constexpr size_t OF_W1L = OF_W1H + SZ_W1;
constexpr size_t OF_W2H = OF_W1L + SZ_W1;
constexpr size_t OF_W2L = OF_W2H + SZ_W1;
constexpr size_t G_TOTAL = OF_W2L + SZ_W1;

__device__ __align__(1024) unsigned char g_mem[G_TOTAL];

// ============================ PTX helpers ==================================

__device__ __forceinline__ uint32_t smem_u32(const void* p) {
    uint32_t a;
    asm("{ .reg .u64 t; cvta.to.shared.u64 t, %1; cvt.u32.u64 %0, t; }"
        : "=r"(a) : "l"(p));
    return a;
}

#define CP16(sa, ga)                                                            \
    asm volatile("cp.async.ca.shared.global [%0], [%1], 16;"                    \
                 :: "r"(sa), "l"(__cvta_generic_to_global(ga)))
#define CP_COMMIT() asm volatile("cp.async.commit_group;" ::: "memory")
#define CP_WAIT0()  asm volatile("cp.async.wait_group 0;" ::: "memory")
#define CP_WAIT1()  asm volatile("cp.async.wait_group 1;" ::: "memory")

#define LDSM4(r, addr)                                                          \
    asm volatile("ldmatrix.sync.aligned.m8n8.x4.shared.b16 {%0,%1,%2,%3}, [%4];"\
        : "=r"((r)[0]), "=r"((r)[1]), "=r"((r)[2]), "=r"((r)[3]) : "r"(addr))

#define MMA_BF16(d, a, b0, b1)                                                  \
    asm volatile("mma.sync.aligned.m16n8k16.row.col.f32.bf16.bf16.f32 "         \
        "{%0,%1,%2,%3}, {%4,%5,%6,%7}, {%8,%9}, {%0,%1,%2,%3};"                 \
        : "+f"((d)[0]), "+f"((d)[1]), "+f"((d)[2]), "+f"((d)[3])                \
        : "r"((a)[0]), "r"((a)[1]), "r"((a)[2]), "r"((a)[3]), "r"(b0), "r"(b1))

__device__ __forceinline__ void split_bf16(float v, __nv_bfloat16& h, __nv_bfloat16& l) {
    h = __float2bfloat16(v);
    l = __float2bfloat16(v - __bfloat162float(h));
}

__device__ __forceinline__ uint32_t bf2_u32(__nv_bfloat16 a, __nv_bfloat16 b) {
    union { __nv_bfloat162 v; uint32_t u; } cvt;
    cvt.v = __halves2bfloat162(a, b);
    return cvt.u;
}

__device__ __forceinline__ void split2_pack(float v0, float v1,
                                            uint32_t& hi, uint32_t& lo) {
    __nv_bfloat16 h0, l0, h1, l1;
    split_bf16(v0, h0, l0);
    split_bf16(v1, h1, l1);
    hi = bf2_u32(h0, h1);
    lo = bf2_u32(l0, l1);
}

__device__ __forceinline__ float ex2(float x) {
    float r;
    asm("ex2.approx.ftz.f32 %0, %1;" : "=f"(r) : "f"(x));
    return r;
}

// ================== weight prep: all weights, one launch ===================
struct WprepP {
    const float* src[6];
    __nv_bfloat16 *dh[6], *dl[6];
};

__global__ __launch_bounds__(256) void wprep_all(WprepP p)
{
    __shared__ float tile[32][33];
    int bid = blockIdx.x;
    int g, layer, kt, nt, Kd, N;
    if (bid < 1536) {
        g = bid / 384; int r = bid % 384;
        layer = r >> 6; int t = r & 63;
        kt = t >> 3; nt = t & 7; Kd = 256; N = 256;
    } else if (bid < 3072) {
        g = 4; int r = bid - 1536;
        layer = r >> 8; int t = r & 255;
        kt = t >> 5; nt = t & 31; Kd = 256; N = 1024;
    } else {
        g = 5; int r = bid - 3072;
        layer = r >> 8; int t = r & 255;
        kt = t >> 3; nt = t & 7; Kd = 1024; N = 256;
    }
    const int k0 = kt << 5, n0 = nt << 5;
    const int tx = threadIdx.x & 31, ty = threadIdx.x >> 5;

    const float* Wp = p.src[g] + (size_t)layer * Kd * N;
#pragma unroll
    for (int r = ty; r < 32; r += 8)
        tile[r][tx] = Wp[(size_t)(k0 + r) * N + n0 + tx];
    __syncthreads();

    __nv_bfloat16* Hp = p.dh[g] + ((size_t)layer * N + n0) * Kd + k0;
    __nv_bfloat16* Lp = p.dl[g] + ((size_t)layer * N + n0) * Kd + k0;
#pragma unroll
    for (int r = ty; r < 32; r += 8) {
        float v = tile[tx][r];
        __nv_bfloat16 h, lo; split_bf16(v, h, lo);
        Hp[(size_t)r * Kd + tx] = h;
        Lp[(size_t)r * Kd + tx] = lo;
    }
}

// ============================ bf16x3 GEMM ==================================
struct GemmP {
    const __nv_bfloat16 *Ah[3], *Al[3], *Wh[3], *Wl[3];
    const float* bias[3];
    float* C[3];
    __nv_bfloat16 *Ch[3], *Cl[3];
};

#define G2_AH 0
#define G2_AL 5120
#define G2_BH 10240
#define G2_BL 20480
#define G2_BUF 30720
#define G2_SMEM (2 * G2_BUF)

__global__ __launch_bounds__(128) void gemm2(GemmP p, int Ncols, int Kd, int mode)
{
    extern __shared__ __align__(16) char smem[];
    const uint32_t sb = smem_u32(smem);

    const int z    = blockIdx.z;
    const __nv_bfloat16* Ah = p.Ah[z];
    const __nv_bfloat16* Al = p.Al[z];
    const __nv_bfloat16* Wh = p.Wh[z];
    const __nv_bfloat16* Wl = p.Wl[z];

    const int tid  = threadIdx.x;
    const int lane = tid & 31;
    const int wn   = tid >> 5;
    const int bm   = blockIdx.y << 6;
    const int bn   = blockIdx.x << 7;

    float acc[4][4][4];
#pragma unroll
    for (int i = 0; i < 4; i++)
#pragma unroll
        for (int j = 0; j < 4; j++)
#pragma unroll
            for (int q = 0; q < 4; q++) acc[i][j][q] = 0.0f;

    const int a_r = lane & 15;
    const int a_c = (lane >> 4) << 3;
    const int b_r = wn * 32 + (lane & 7) + ((lane >> 4) << 3);
    const int b_c = ((lane >> 3) & 1) << 3;

    const int nc = Kd >> 5;

    auto issue = [&](int c, int buf) {
        const uint32_t sa = sb + buf * G2_BUF;
        const size_t kb = (size_t)(c << 5) * 2;
#pragma unroll
        for (int i = 0; i < 2; i++) {
            int s = tid + (i << 7);
            int row = s >> 2, seg = s & 3;
            size_t go = ((size_t)(bm + row) * Kd) * 2 + kb + seg * 16;
            uint32_t so = sa + row * 80 + seg * 16;
            CP16(so + G2_AH, (const char*)Ah + go);
            CP16(so + G2_AL, (const char*)Al + go);
        }
#pragma unroll
        for (int i = 0; i < 4; i++) {
            int s = tid + (i << 7);
            int row = s >> 2, seg = s & 3;
            size_t go = ((size_t)(bn + row) * Kd) * 2 + kb + seg * 16;
            uint32_t so = sa + row * 80 + seg * 16;
            CP16(so + G2_BH, (const char*)Wh + go);
            CP16(so + G2_BL, (const char*)Wl + go);
        }
        CP_COMMIT();
    };

    issue(0, 0);

    for (int c = 0; c < nc; c++) {
        const int buf = c & 1;
        if (c + 1 < nc) { issue(c + 1, buf ^ 1); CP_WAIT1(); }
        else           { CP_WAIT0(); }
        __syncthreads();

        const uint32_t sa = sb + buf * G2_BUF;
#pragma unroll
        for (int ks = 0; ks < 2; ks++) {
            uint32_t ah[4][4], al[4][4];
#pragma unroll
            for (int mb = 0; mb < 4; mb++) {
                uint32_t ao = sa + (uint32_t)(a_r + mb * 16) * 80 + (ks * 16 + a_c) * 2;
                LDSM4(ah[mb], ao + G2_AH);
                LDSM4(al[mb], ao + G2_AL);
            }
            uint32_t bh[2][4], bl[2][4];
#pragma unroll
            for (int np = 0; np < 2; np++) {
                uint32_t bo = sa + (uint32_t)(b_r + np * 16) * 80 + (ks * 16 + b_c) * 2;
                LDSM4(bh[np], bo + G2_BH);
                LDSM4(bl[np], bo + G2_BL);
            }
#pragma unroll
            for (int mb = 0; mb < 4; mb++)
#pragma unroll
                for (int nb = 0; nb < 4; nb++) {
                    const int np = nb >> 1, sl = (nb & 1) << 1;
                    MMA_BF16(acc[mb][nb], ah[mb], bh[np][sl], bh[np][sl + 1]);
                    MMA_BF16(acc[mb][nb], al[mb], bh[np][sl], bh[np][sl + 1]);
                    MMA_BF16(acc[mb][nb], ah[mb], bl[np][sl], bl[np][sl + 1]);
                }
        }
        __syncthreads();
    }

    const float* bias = p.bias[z];
    const int r0 = bm + (lane >> 2);
    const int c0 = bn + wn * 32 + ((lane & 3) << 1);

    if (mode == 2) {
        __nv_bfloat16* Ch = p.Ch[z];
        __nv_bfloat16* Cl = p.Cl[z];
#pragma unroll
        for (int mb = 0; mb < 4; mb++)
#pragma unroll
            for (int nb = 0; nb < 4; nb++) {
                int rr = r0 + mb * 16, cc = c0 + nb * 8;
                float bb0 = bias[cc], bb1 = bias[cc + 1];
#pragma unroll
                for (int hrow = 0; hrow < 2; hrow++) {
                    int r = rr + hrow * 8;
                    float v0 = fmaxf(acc[mb][nb][2 * hrow]     + bb0, 0.0f);
                    float v1 = fmaxf(acc[mb][nb][2 * hrow + 1] + bb1, 0.0f);
                    uint32_t hw, lw;
                    split2_pack(v0, v1, hw, lw);
                    *(uint32_t*)(Ch + (size_t)r * Ncols + cc) = hw;
                    *(uint32_t*)(Cl + (size_t)r * Ncols + cc) = lw;
                }
            }
    } else {    // mode 3: attention QKV layout
        __nv_bfloat16* Ch = p.Ch[z];
        __nv_bfloat16* Cl = p.Cl[z];
#pragma unroll
        for (int mb = 0; mb < 4; mb++)
#pragma unroll
            for (int nb = 0; nb < 4; nb++) {
                int rr = r0 + mb * 16, cc = c0 + nb * 8;
                float bb0 = bias[cc], bb1 = bias[cc + 1];
                int bh = ((rr >> 10) << 3) + (cc >> 5);
                int d  = cc & 31;
#pragma unroll
                for (int hrow = 0; hrow < 2; hrow++) {
                    int r = rr + hrow * 8;
                    int q = r & 1023;
                    float v0 = acc[mb][nb][2 * hrow]     + bb0;
                    float v1 = acc[mb][nb][2 * hrow + 1] + bb1;
                    __nv_bfloat16 h0, l0, h1, l1;
                    split_bf16(v0, h0, l0);
                    split_bf16(v1, h1, l1);
                    if (z < 2) {
                        size_t a = ((size_t)bh * 1024 + q) * 32 + d;
                        *(uint32_t*)(Ch + a) = bf2_u32(h0, h1);
                        *(uint32_t*)(Cl + a) = bf2_u32(l0, l1);
                    } else {
                        size_t a = ((size_t)bh * 32 + d) * 1024 + q;
                        Ch[a] = h0; Ch[a + 1024] = h1;
                        Cl[a] = l0; Cl[a + 1024] = l1;
                    }
                }
            }
    }
}

// ================= GEMM + LayerNorm fused (O-proj / FFN2) ==================
// 512 threads: 16 warps, warp w owns output cols [16w, 16w+16).
// Tile 32 rows x 256 cols, K-chunk 32, cp.async x2 buffers.
#define GL_AH 0
#define GL_AL 2560
#define GL_BH 5120
#define GL_BL 25600
#define GL_BUF 46080
#define GL_RED   92160          // 32 rows x 16 warps x float2 = 4096 B
#define GL_BIAS  96256
#define GL_GAM   97280
#define GL_BET   98304
#define GL_SMEM  99328

__global__ __launch_bounds__(512) void gemm_ln(
    const __nv_bfloat16* __restrict__ Ah, const __nv_bfloat16* __restrict__ Al,
    const __nv_bfloat16* __restrict__ Wh, const __nv_bfloat16* __restrict__ Wl,
    const float* __restrict__ bias, const float* __restrict__ gam,
    const float* __restrict__ bet, const float* __restrict__ res,
    float* __restrict__ Xout, __nv_bfloat16* __restrict__ Xh,
    __nv_bfloat16* __restrict__ Xl,
    float* __restrict__ out, const int* __restrict__ il,
    const int* __restrict__ fnum,
    int Kd, int mode)
{
    extern __shared__ __align__(16) char smem[];
    const uint32_t sb = smem_u32(smem);

    const int tid  = threadIdx.x;
    const int lane = tid & 31;
    const int w    = tid >> 5;          // 0..15, owns cols [16w, 16w+16)
    const int bm   = blockIdx.y << 5;

    if (tid < 256) {
        ((float*)(smem + GL_BIAS))[tid] = bias[tid];
        ((float*)(smem + GL_GAM))[tid]  = gam[tid];
        ((float*)(smem + GL_BET))[tid]  = bet[tid];
    }

    float acc[2][2][4];
#pragma unroll
    for (int i = 0; i < 2; i++)
#pragma unroll
        for (int j = 0; j < 2; j++)
#pragma unroll
            for (int q = 0; q < 4; q++) acc[i][j][q] = 0.0f;

    const int a_r = lane & 15;
    const int a_c = (lane >> 4) << 3;
    const int b_rr = (lane & 7) + ((lane >> 4) << 3);
    const int b_cc = ((lane >> 3) & 1) << 3;

    const int nc = Kd >> 5;

    auto issue = [&](int c, int buf) {
        const uint32_t sa = sb + buf * GL_BUF;
        const size_t kb = (size_t)(c << 5) * 2;
        if (tid < 128) {                       // A: 32 rows x 4 segs
            int row = tid >> 2, seg = tid & 3;
            size_t go = ((size_t)(bm + row) * Kd) * 2 + kb + seg * 16;
            uint32_t so = sa + row * 80 + seg * 16;
            CP16(so + GL_AH, (const char*)Ah + go);
            CP16(so + GL_AL, (const char*)Al + go);
        }
#pragma unroll
        for (int i = 0; i < 2; i++) {          // B: 256 rows x 4 segs = 1024 ops
            int s = tid + (i << 9);
            int row = s >> 2, seg = s & 3;
            size_t go = ((size_t)row * Kd) * 2 + kb + seg * 16;
            uint32_t so = sa + row * 80 + seg * 16;
            CP16(so + GL_BH, (const char*)Wh + go);
            CP16(so + GL_BL, (const char*)Wl + go);
        }
        CP_COMMIT();
    };

    issue(0, 0);

    for (int c = 0; c < nc; c++) {
        const int buf = c & 1;
        if (c + 1 < nc) { issue(c + 1, buf ^ 1); CP_WAIT1(); }
        else           { CP_WAIT0(); }
        __syncthreads();

        const uint32_t sa = sb + buf * GL_BUF;
#pragma unroll
        for (int ks = 0; ks < 2; ks++) {
            uint32_t ah[2][4], al[2][4];
#pragma unroll
            for (int mb = 0; mb < 2; mb++) {
                uint32_t ao = sa + (uint32_t)(mb * 16 + a_r) * 80 + (ks * 16 + a_c) * 2;
                LDSM4(ah[mb], ao + GL_AH);
                LDSM4(al[mb], ao + GL_AL);
            }
            uint32_t bh[4], bl[4];
            {
                uint32_t bo = sa + (uint32_t)(w * 16 + b_rr) * 80
                            + (ks * 16 + b_cc) * 2;
                LDSM4(bh, bo + GL_BH);
                LDSM4(bl, bo + GL_BL);
            }
#pragma unroll
            for (int mb = 0; mb < 2; mb++)
#pragma unroll
                for (int nb = 0; nb < 2; nb++) {
                    const int sl = nb << 1;
                    MMA_BF16(acc[mb][nb], ah[mb], bh[sl], bh[sl + 1]);
                    MMA_BF16(acc[mb][nb], al[mb], bh[sl], bh[sl + 1]);
                    MMA_BF16(acc[mb][nb], ah[mb], bl[sl], bl[sl + 1]);
                }
        }
        __syncthreads();
    }

    // ---- epilogue: v = res + C + bias; reduce for LN ----
    const float* bias_s = (const float*)(smem + GL_BIAS);
    float2* red = (float2*)(smem + GL_RED);

#pragma unroll
    for (int mb = 0; mb < 2; mb++) {
        float sA = 0.f, qA = 0.f, sB = 0.f, qB = 0.f;
#pragma unroll
        for (int nb = 0; nb < 2; nb++) {
            int cc = w * 16 + nb * 8 + ((lane & 3) << 1);
            int rA = bm + mb * 16 + (lane >> 2);
            int rB = rA + 8;
            float2 resA = *(const float2*)(res + (size_t)rA * Dn + cc);
            float2 resB = *(const float2*)(res + (size_t)rB * Dn + cc);
            float bb0 = bias_s[cc], bb1 = bias_s[cc + 1];
            float v;
            v = acc[mb][nb][0] + bb0 + resA.x; acc[mb][nb][0] = v; sA += v; qA += v * v;
            v = acc[mb][nb][1] + bb1 + resA.y; acc[mb][nb][1] = v; sA += v; qA += v * v;
            v = acc[mb][nb][2] + bb0 + resB.x; acc[mb][nb][2] = v; sB += v; qB += v * v;
            v = acc[mb][nb][3] + bb1 + resB.y; acc[mb][nb][3] = v; sB += v; qB += v * v;
        }
        sA += __shfl_xor_sync(0xffffffffu, sA, 1); qA += __shfl_xor_sync(0xffffffffu, qA, 1);
        sA += __shfl_xor_sync(0xffffffffu, sA, 2); qA += __shfl_xor_sync(0xffffffffu, qA, 2);
        sB += __shfl_xor_sync(0xffffffffu, sB, 1); qB += __shfl_xor_sync(0xffffffffu, qB, 1);
        sB += __shfl_xor_sync(0xffffffffu, sB, 2); qB += __shfl_xor_sync(0xffffffffu, qB, 2);
        if ((lane & 3) == 0) {
            int rlA = mb * 16 + (lane >> 2);
            red[rlA * 16 + w] = make_float2(sA, qA);
            red[(rlA + 8) * 16 + w] = make_float2(sB, qB);
        }
    }
    __syncthreads();

    const float* gam_s = (const float*)(smem + GL_GAM);
    const float* bet_s = (const float*)(smem + GL_BET);
    const int b = bm >> 10;
    int fn = 0;
    if (mode == 2) fn = fnum[b];

#pragma unroll
    for (int mb = 0; mb < 2; mb++) {
#pragma unroll
        for (int hrow = 0; hrow < 2; hrow++) {
            int rl = mb * 16 + hrow * 8 + (lane >> 2);
            int row = bm + rl;
            float su = 0.f, sq = 0.f;
#pragma unroll
            for (int w2 = 0; w2 < 16; w2++) {
                float2 r2 = red[rl * 16 + w2];
                su += r2.x; sq += r2.y;
            }
            float mu = su * (1.0f / Dn);
            float var = sq * (1.0f / Dn) - mu * mu;
            float rs = rsqrtf(var + 1e-5f);

            if (mode == 1) {
#pragma unroll
                for (int nb = 0; nb < 2; nb++) {
                    int cc = w * 16 + nb * 8 + ((lane & 3) << 1);
                    float y0 = (acc[mb][nb][2 * hrow]     - mu) * rs * gam_s[cc]     + bet_s[cc];
                    float y1 = (acc[mb][nb][2 * hrow + 1] - mu) * rs * gam_s[cc + 1] + bet_s[cc + 1];
                    size_t a = (size_t)row * Dn + cc;
                    *(float2*)(Xout + a) = make_float2(y0, y1);
                    uint32_t hw, lw;
                    split2_pack(y0, y1, hw, lw);
                    *(uint32_t*)(Xh + a) = hw;
                    *(uint32_t*)(Xl + a) = lw;
                }
            } else {
                int j = row & 1023;
                if (j < fn) {
                    int idx = il[row];
                    float* op = out + ((size_t)b * NN + idx) * Dn;
#pragma unroll
                    for (int nb = 0; nb < 2; nb++) {
                        int cc = w * 16 + nb * 8 + ((lane & 3) << 1);
                        float y0 = (acc[mb][nb][2 * hrow]     - mu) * rs * gam_s[cc]     + bet_s[cc];
                        float y1 = (acc[mb][nb][2 * hrow + 1] - mu) * rs * gam_s[cc + 1] + bet_s[cc + 1];
                        *(float2*)(op + cc) = make_float2(y0, y1);
                    }
                }
            }
        }
    }
}

// ====================== tensor-core flash attention ========================
#define AT_QH 0
#define AT_QL 10240
#define AT_K  20480             // + buf*10240 : Kh(5120) Kl(5120)
#define AT_V  40960             // + buf*9216  : Vh(4608) Vl(4608)
#define AT_SMEM 59392
#define BETA 0.2550165213f      // log2(e)/sqrt(32)

__global__ __launch_bounds__(256, 2) void attn_tc(
    const __nv_bfloat16* __restrict__ Qh, const __nv_bfloat16* __restrict__ Ql,
    const __nv_bfloat16* __restrict__ Kh, const __nv_bfloat16* __restrict__ Kl,
    const __nv_bfloat16* __restrict__ Vh, const __nv_bfloat16* __restrict__ Vl,
    __nv_bfloat16* __restrict__ Oh, __nv_bfloat16* __restrict__ Ol)
{
    extern __shared__ __align__(16) char smem[];
    const uint32_t sb = smem_u32(smem);

    const int tid  = threadIdx.x;
    const int lane = tid & 31;
    const int warp = tid >> 5;
    const int bh   = blockIdx.x;
    const int q0   = blockIdx.y << 7;

    {
        const char* gqh = (const char*)(Qh + ((size_t)bh * 1024 + q0) * 32);
        const char* gql = (const char*)(Ql + ((size_t)bh * 1024 + q0) * 32);
#pragma unroll
        for (int i = 0; i < 2; i++) {
            int s = tid + (i << 8);
            int row = s >> 2, seg = s & 3;
            size_t go = (size_t)row * 64 + seg * 16;
            uint32_t so = (uint32_t)row * 80 + seg * 16;
            CP16(sb + AT_QH + so, gqh + go);
            CP16(sb + AT_QL + so, gql + go);
        }
    }

    auto issueKV = [&](int c, int buf) {
        const int kc = c << 6;
        const uint32_t sk = sb + AT_K + buf * 10240;
        const uint32_t sv = sb + AT_V + buf * 9216;
        {
            const char* gkh = (const char*)(Kh + ((size_t)bh * 1024 + kc) * 32);
            const char* gkl = (const char*)(Kl + ((size_t)bh * 1024 + kc) * 32);
            int row = tid >> 2, seg = tid & 3;
            size_t go = (size_t)row * 64 + seg * 16;
            uint32_t so = (uint32_t)row * 80 + seg * 16;
            CP16(sk + so, gkh + go);
            CP16(sk + 5120 + so, gkl + go);
        }
        {
            const char* gvh = (const char*)(Vh + (size_t)bh * 32 * 1024 + kc);
            const char* gvl = (const char*)(Vl + (size_t)bh * 32 * 1024 + kc);
            int d = tid >> 3, seg = tid & 7;
            size_t go = (size_t)d * 2048 + seg * 16;
            uint32_t so = (uint32_t)d * 144 + seg * 16;
            CP16(sv + so, gvh + go);
            CP16(sv + 4608 + so, gvl + go);
        }
        CP_COMMIT();
    };

    issueKV(0, 0);

    float o[4][4];
    float m[2], l[2];
#pragma unroll
    for (int b = 0; b < 4; b++)
#pragma unroll
        for (int q = 0; q < 4; q++) o[b][q] = 0.0f;
    m[0] = m[1] = -1e30f; l[0] = l[1] = 0.0f;

    uint32_t qfh[2][4], qfl[2][4];

    const int a_r = lane & 15;
    const int a_c = (lane >> 4) << 3;
    const int b_rr = (lane & 7) + ((lane >> 4) << 3);
    const int b_cc = ((lane >> 3) & 1) << 3;

    for (int c = 0; c < 16; c++) {
        const int buf = c & 1;
        if (c + 1 < 16) { issueKV(c + 1, buf ^ 1); CP_WAIT1(); }
        else            { CP_WAIT0(); }
        __syncthreads();

        if (c == 0) {
#pragma unroll
            for (int kk = 0; kk < 2; kk++) {
                uint32_t ao = (uint32_t)(warp * 16 + a_r) * 80 + (kk * 16 + a_c) * 2;
                LDSM4(qfh[kk], sb + AT_QH + ao);
                LDSM4(qfl[kk], sb + AT_QL + ao);
            }
        }

        const uint32_t sk = sb + AT_K + buf * 10240;
        const uint32_t sv = sb + AT_V + buf * 9216;

        float s[8][4];
#pragma unroll
        for (int b = 0; b < 8; b++)
#pragma unroll
            for (int q = 0; q < 4; q++) s[b][q] = 0.0f;

#pragma unroll
        for (int g = 0; g < 4; g++) {
            uint32_t kfh[2][4], kfl[2][4];
#pragma unroll
            for (int kk = 0; kk < 2; kk++) {
                uint32_t bo = (uint32_t)(g * 16 + b_rr) * 80 + (kk * 16 + b_cc) * 2;
                LDSM4(kfh[kk], sk + bo);
                LDSM4(kfl[kk], sk + 5120 + bo);
            }
#pragma unroll
            for (int nb = 0; nb < 2; nb++) {
                const int nt = g * 2 + nb, sl = nb << 1;
#pragma unroll
                for (int kk = 0; kk < 2; kk++) {
                    MMA_BF16(s[nt], qfh[kk], kfh[kk][sl], kfh[kk][sl + 1]);
                    MMA_BF16(s[nt], qfl[kk], kfh[kk][sl], kfh[kk][sl + 1]);
                    MMA_BF16(s[nt], qfh[kk], kfl[kk][sl], kfl[kk][sl + 1]);
                }
            }
        }

        float alpha[2], mn2[2];
#pragma unroll
        for (int h = 0; h < 2; h++) {
            float mx = -1e30f;
#pragma unroll
            for (int nt = 0; nt < 8; nt++) {
                mx = fmaxf(mx, s[nt][2 * h]);
                mx = fmaxf(mx, s[nt][2 * h + 1]);
            }
            mx = fmaxf(mx, __shfl_xor_sync(0xffffffffu, mx, 1));
            mx = fmaxf(mx, __shfl_xor_sync(0xffffffffu, mx, 2));
            float mn = fmaxf(m[h], mx);
            alpha[h] = ex2((m[h] - mn) * BETA);
            mn2[h] = mn;
            m[h] = mn;
        }
        {
            float nm0 = mn2[0] * BETA, nm1 = mn2[1] * BETA;
#pragma unroll
            for (int nt = 0; nt < 8; nt++) {
                s[nt][0] = ex2(fmaf(s[nt][0], BETA, -nm0));
                s[nt][1] = ex2(fmaf(s[nt][1], BETA, -nm0));
                s[nt][2] = ex2(fmaf(s[nt][2], BETA, -nm1));
                s[nt][3] = ex2(fmaf(s[nt][3], BETA, -nm1));
            }
        }
#pragma unroll
        for (int h = 0; h < 2; h++) {
            float su = 0.0f;
#pragma unroll
            for (int nt = 0; nt < 8; nt++)
                su += s[nt][2 * h] + s[nt][2 * h + 1];
            su += __shfl_xor_sync(0xffffffffu, su, 1);
            su += __shfl_xor_sync(0xffffffffu, su, 2);
            l[h] = l[h] * alpha[h] + su;
        }
#pragma unroll
        for (int nb = 0; nb < 4; nb++) {
            o[nb][0] *= alpha[0];
            o[nb][1] *= alpha[0];
            o[nb][2] *= alpha[1];
            o[nb][3] *= alpha[1];
        }

#pragma unroll
        for (int kt = 0; kt < 4; kt++) {
            uint32_t vfh[2][4], vfl[2][4];
#pragma unroll
            for (int g = 0; g < 2; g++) {
                uint32_t bo = (uint32_t)(g * 16 + b_rr) * 144 + (kt * 16 + b_cc) * 2;
                LDSM4(vfh[g], sv + bo);
                LDSM4(vfl[g], sv + 4608 + bo);
            }
            const int t0 = kt * 2, t1 = kt * 2 + 1;
            uint32_t ph[4], pl[4];
            split2_pack(s[t0][0], s[t0][1], ph[0], pl[0]);
            split2_pack(s[t0][2], s[t0][3], ph[1], pl[1]);
            split2_pack(s[t1][0], s[t1][1], ph[2], pl[2]);
            split2_pack(s[t1][2], s[t1][3], ph[3], pl[3]);
#pragma unroll
            for (int nb = 0; nb < 4; nb++) {
                const int g = nb >> 1, sl = (nb & 1) << 1;
                MMA_BF16(o[nb], ph, vfh[g][sl], vfh[g][sl + 1]);
                MMA_BF16(o[nb], pl, vfh[g][sl], vfh[g][sl + 1]);
                MMA_BF16(o[nb], ph, vfl[g][sl], vfl[g][sl + 1]);
            }
        }
        __syncthreads();
    }

    const int b  = bh >> 3;
    const int hh = bh & 7;
    {
        float i0 = 1.0f / l[0], i1 = 1.0f / l[1];
#pragma unroll
        for (int h = 0; h < 2; h++) {
            int row = b * 1024 + q0 + warp * 16 + h * 8 + (lane >> 2);
            float inv = h ? i1 : i0;
#pragma unroll
            for (int nb = 0; nb < 4; nb++) {
                int d = nb * 8 + ((lane & 3) << 1);
                float v0 = o[nb][2 * h]     * inv;
                float v1 = o[nb][2 * h + 1] * inv;
                uint32_t hw, lw;
                split2_pack(v0, v1, hw, lw);
                size_t a = (size_t)row * Dn + hh * 32 + d;
                *(uint32_t*)(Oh + a) = hw;
                *(uint32_t*)(Ol + a) = lw;
            }
        }
    }
}

// ---------------------------------------------------------------------------
// Gather + MCSP
// ---------------------------------------------------------------------------
__global__ __launch_bounds__(256) void gather_cls_kernel(
    const float* __restrict__ out, const float* __restrict__ qpos,
    const float* __restrict__ fgs, const int* __restrict__ il,
    const float* __restrict__ Wcls, const float* __restrict__ bcls,
    float* __restrict__ tgt,
    __nv_bfloat16* __restrict__ tgh, __nv_bfloat16* __restrict__ tgl,
    __nv_bfloat16* __restrict__ qkh, __nv_bfloat16* __restrict__ qkl)
{
    __shared__ float qs[Dn];
    __shared__ float sc[16];

    int row = blockIdx.x;
    int b   = row >> 10;
    int t   = threadIdx.x;
    int lane = t & 31, w = t >> 5;
    int idx = il[row];
    size_t src = ((size_t)b * NN + idx) * Dn + t;
    float qv = out[src];
    qs[t] = qv;
    __syncthreads();

#pragma unroll
    for (int ci = 0; ci < 2; ci++) {
        int c = w + ci * 8;
        if (c < NCLSn) {
            float sum = 0.0f;
#pragma unroll
            for (int j = 0; j < 8; j++) {
                int e = lane + (j << 5);
                sum += qs[e] * Wcls[e * NCLSn + c];
            }
#pragma unroll
            for (int o = 16; o; o >>= 1) sum += __shfl_down_sync(0xffffffffu, sum, o);
            if (lane == 0) sc[c] = sum + bcls[c];
        }
    }
    __syncthreads();

    float mx = sc[0];
#pragma unroll
    for (int c = 1; c < NCLSn; c++) mx = fmaxf(mx, sc[c]);
    float mc = (1.0f / (1.0f + __expf(-mx))) * fgs[(size_t)b * NN + idx];

    float tv = tgt[(size_t)row * Dn + t] = qv * mc;
    float qk = tv + qpos[src];
    size_t i = (size_t)row * Dn + t;
    __nv_bfloat16 h, lo;
    split_bf16(tv, h, lo); tgh[i] = h; tgl[i] = lo;
    split_bf16(qk, h, lo); qkh[i] = h; qkl[i] = lo;
}

// ---------------------------------------------------------------------------
// Host-side orchestration
// ---------------------------------------------------------------------------
extern "C" void kernel_launch(void* const* d_in, const int* in_sizes, int n_in,
                              void* d_out, int out_size)
{
    int qp_idx = (in_sizes[1] == 8) ? 4 : 1;

    const float* query = (const float*)d_in[0];
    const float* qpos  = (const float*)d_in[qp_idx];
    const float* fgs   = (const float*)d_in[6];
    const int*   fnum  = (const int*)d_in[7];
    const int*   inds  = (const int*)d_in[8];
    const float* Wq = (const float*)d_in[9],  *bq = (const float*)d_in[10];
    const float* Wk = (const float*)d_in[11], *bk = (const float*)d_in[12];
    const float* Wv = (const float*)d_in[13], *bv = (const float*)d_in[14];
    const float* Wo = (const float*)d_in[15], *bo = (const float*)d_in[16];
    const float* g1 = (const float*)d_in[17], *be1 = (const float*)d_in[18];
    const float* W1 = (const float*)d_in[19], *b1 = (const float*)d_in[20];
    const float* W2 = (const float*)d_in[21], *b2 = (const float*)d_in[22];
    const float* g2 = (const float*)d_in[23], *be2 = (const float*)d_in[24];
    const float* Wcls = (const float*)d_in[25], *bcls = (const float*)d_in[26];

    float* out = (float*)d_out;

    unsigned char* base = nullptr;
    cudaGetSymbolAddress((void**)&base, g_mem);
#define FP(off)  ((float*)(base + (off)))
#define BF(off)  ((__nv_bfloat16*)(base + (off)))

    float *tgt = FP(OF_TGT), *Xb = FP(OF_XB);
    __nv_bfloat16 *qkh = BF(OF_QKH), *qkl = BF(OF_QKL);
    __nv_bfloat16 *tgh = BF(OF_TGH), *tgl = BF(OF_TGL);
    __nv_bfloat16 *qh  = BF(OF_QH),  *ql  = BF(OF_QL);
    __nv_bfloat16 *kh  = BF(OF_KH),  *kl  = BF(OF_KL);
    __nv_bfloat16 *vh  = BF(OF_VH),  *vl  = BF(OF_VL);
    __nv_bfloat16 *ath = BF(OF_ATH), *atl = BF(OF_ATL);
    __nv_bfloat16 *xh  = BF(OF_XH),  *xl  = BF(OF_XL);
    __nv_bfloat16 *hh  = BF(OF_HH),  *hl  = BF(OF_HL);
    __nv_bfloat16 *wqh = BF(OF_WQH), *wql = BF(OF_WQL);
    __nv_bfloat16 *wkh = BF(OF_WKH), *wkl = BF(OF_WKL);
    __nv_bfloat16 *wvh = BF(OF_WVH), *wvl = BF(OF_WVL);
    __nv_bfloat16 *woh = BF(OF_WOH), *wol = BF(OF_WOL);
    __nv_bfloat16 *w1h = BF(OF_W1H), *w1l = BF(OF_W1L);
    __nv_bfloat16 *w2h = BF(OF_W2H), *w2l = BF(OF_W2L);

    cudaFuncSetAttribute(gemm2, cudaFuncAttributeMaxDynamicSharedMemorySize, G2_SMEM);
    cudaFuncSetAttribute(gemm_ln, cudaFuncAttributeMaxDynamicSharedMemorySize, GL_SMEM);
    cudaFuncSetAttribute(attn_tc, cudaFuncAttributeMaxDynamicSharedMemorySize, AT_SMEM);

    {
        WprepP wp{};
        wp.src[0] = Wq; wp.dh[0] = wqh; wp.dl[0] = wql;
        wp.src[1] = Wk; wp.dh[1] = wkh; wp.dl[1] = wkl;
        wp.src[2] = Wv; wp.dh[2] = wvh; wp.dl[2] = wvl;
        wp.src[3] = Wo; wp.dh[3] = woh; wp.dl[3] = wol;
        wp.src[4] = W1; wp.dh[4] = w1h; wp.dl[4] = w1l;
        wp.src[5] = W2; wp.dh[5] = w2h; wp.dl[5] = w2l;
        wprep_all<<<4608, 256>>>(wp);
    }

    cudaMemcpyAsync(out, query, sizeof(float) * (size_t)Bn * NN * Dn,
                    cudaMemcpyDeviceToDevice);

    for (int l = 0; l < L_LAYERS; l++) {
        const int* il = inds + (size_t)l * ROWS;
        const size_t wd = (size_t)l * Dn * Dn;
        const size_t wf = (size_t)l * Dn * FFNn;

        gather_cls_kernel<<<ROWS, 256>>>(out, qpos, fgs, il, Wcls, bcls,
                                         tgt, tgh, tgl, qkh, qkl);

        {   // QKV batched -> head layouts
            GemmP p{};
            p.Ah[0] = qkh; p.Al[0] = qkl; p.Wh[0] = wqh + wd; p.Wl[0] = wql + wd;
            p.bias[0] = bq + l * Dn; p.Ch[0] = qh; p.Cl[0] = ql;
            p.Ah[1] = qkh; p.Al[1] = qkl; p.Wh[1] = wkh + wd; p.Wl[1] = wkl + wd;
            p.bias[1] = bk + l * Dn; p.Ch[1] = kh; p.Cl[1] = kl;
            p.Ah[2] = tgh; p.Al[2] = tgl; p.Wh[2] = wvh + wd; p.Wl[2] = wvl + wd;
            p.bias[2] = bv + l * Dn; p.Ch[2] = vh; p.Cl[2] = vl;
            gemm2<<<dim3(2, 64, 3), 128, G2_SMEM>>>(p, Dn, Dn, 3);
        }

        attn_tc<<<dim3(Bn * Hn, Kn / 128), 256, AT_SMEM>>>(qh, ql, kh, kl, vh, vl,
                                                           ath, atl);

        // O projection + LN1 fused (res = tgt) -> Xb, xh, xl
        gemm_ln<<<dim3(1, ROWS / 32), 512, GL_SMEM>>>(
            ath, atl, woh + wd, wol + wd,
            bo + l * Dn, g1 + l * Dn, be1 + l * Dn, tgt,
            Xb, xh, xl, nullptr, nullptr, nullptr, Dn, 1);

        {   // FFN1 (relu, bf16 split out)
            GemmP p{};
            p.Ah[0] = xh; p.Al[0] = xl; p.Wh[0] = w1h + wf; p.Wl[0] = w1l + wf;
            p.bias[0] = b1 + l * FFNn; p.Ch[0] = hh; p.Cl[0] = hl;
            gemm2<<<dim3(8, 64, 1), 128, G2_SMEM>>>(p, FFNn, Dn, 2);
        }

        // FFN2 + LN2 + ragged scatter fused (res = Xb) -> out
        gemm_ln<<<dim3(1, ROWS / 32), 512, GL_SMEM>>>(
            hh, hl, w2h + wf, w2l + wf,
            b2 + l * Dn, g2 + l * Dn, be2 + l * Dn, Xb,
            nullptr, nullptr, nullptr, out, il, fnum, FFNn, 2);
    }
}

// round 10
// speedup vs baseline: 1.0760x; 1.0760x over previous
#include <cuda_runtime.h>
#include <cuda_bf16.h>
#include <cstdint>

// ---------------------------------------------------------------------------
// Focus-DETR encoder — round 10: gemm_ln reverted to 256-thread (round-8)
// config; attention PV drops the V-lo term (V bf16-rounded, error ~1e-5).
// ---------------------------------------------------------------------------

#define L_LAYERS 6
#define Bn 4
#define NN 23890
#define Kn 1024
#define Dn 256
#define Hn 8
#define HDn 32
#define FFNn 1024
#define NCLSn 15

#define ROWS (Bn * Kn)          // 4096
#define RD   (ROWS * Dn)        // 1048576 elements

// ---------------- scratch carving ----------------
constexpr size_t SZ_F  = (size_t)RD * 4;
constexpr size_t SZ_B  = (size_t)RD * 2;
constexpr size_t SZ_H  = (size_t)ROWS * FFNn * 2;
constexpr size_t SZ_WD = (size_t)L_LAYERS * Dn * Dn * 2;
constexpr size_t SZ_W1 = (size_t)L_LAYERS * Dn * FFNn * 2;

constexpr size_t OF_TGT = 0;
constexpr size_t OF_XB  = OF_TGT + SZ_F;
constexpr size_t OF_QKH = OF_XB  + SZ_F;
constexpr size_t OF_QKL = OF_QKH + SZ_B;
constexpr size_t OF_TGH = OF_QKL + SZ_B;
constexpr size_t OF_TGL = OF_TGH + SZ_B;
constexpr size_t OF_QH  = OF_TGL + SZ_B;
constexpr size_t OF_QL  = OF_QH  + SZ_B;
constexpr size_t OF_KH  = OF_QL  + SZ_B;
constexpr size_t OF_KL  = OF_KH  + SZ_B;
constexpr size_t OF_VH  = OF_KL  + SZ_B;
constexpr size_t OF_VL  = OF_VH  + SZ_B;
constexpr size_t OF_ATH = OF_VL  + SZ_B;
constexpr size_t OF_ATL = OF_ATH + SZ_B;
constexpr size_t OF_XH  = OF_ATL + SZ_B;
constexpr size_t OF_XL  = OF_XH  + SZ_B;
constexpr size_t OF_HH  = OF_XL  + SZ_B;
constexpr size_t OF_HL  = OF_HH  + SZ_H;
constexpr size_t OF_WQH = OF_HL  + SZ_H;
constexpr size_t OF_WQL = OF_WQH + SZ_WD;
constexpr size_t OF_WKH = OF_WQL + SZ_WD;
constexpr size_t OF_WKL = OF_WKH + SZ_WD;
constexpr size_t OF_WVH = OF_WKL + SZ_WD;
constexpr size_t OF_WVL = OF_WVH + SZ_WD;
constexpr size_t OF_WOH = OF_WVL + SZ_WD;
constexpr size_t OF_WOL = OF_WOH + SZ_WD;
constexpr size_t OF_W1H = OF_WOL + SZ_WD;
constexpr size_t OF_W1L = OF_W1H + SZ_W1;
constexpr size_t OF_W2H = OF_W1L + SZ_W1;
constexpr size_t OF_W2L = OF_W2H + SZ_W1;
constexpr size_t G_TOTAL = OF_W2L + SZ_W1;

__device__ __align__(1024) unsigned char g_mem[G_TOTAL];

// ============================ PTX helpers ==================================

__device__ __forceinline__ uint32_t smem_u32(const void* p) {
    uint32_t a;
    asm("{ .reg .u64 t; cvta.to.shared.u64 t, %1; cvt.u32.u64 %0, t; }"
        : "=r"(a) : "l"(p));
    return a;
}

#define CP16(sa, ga)                                                            \
    asm volatile("cp.async.ca.shared.global [%0], [%1], 16;"                    \
                 :: "r"(sa), "l"(__cvta_generic_to_global(ga)))
#define CP_COMMIT() asm volatile("cp.async.commit_group;" ::: "memory")
#define CP_WAIT0()  asm volatile("cp.async.wait_group 0;" ::: "memory")
#define CP_WAIT1()  asm volatile("cp.async.wait_group 1;" ::: "memory")

#define LDSM4(r, addr)                                                          \
    asm volatile("ldmatrix.sync.aligned.m8n8.x4.shared.b16 {%0,%1,%2,%3}, [%4];"\
        : "=r"((r)[0]), "=r"((r)[1]), "=r"((r)[2]), "=r"((r)[3]) : "r"(addr))

#define MMA_BF16(d, a, b0, b1)                                                  \
    asm volatile("mma.sync.aligned.m16n8k16.row.col.f32.bf16.bf16.f32 "         \
        "{%0,%1,%2,%3}, {%4,%5,%6,%7}, {%8,%9}, {%0,%1,%2,%3};"                 \
        : "+f"((d)[0]), "+f"((d)[1]), "+f"((d)[2]), "+f"((d)[3])                \
        : "r"((a)[0]), "r"((a)[1]), "r"((a)[2]), "r"((a)[3]), "r"(b0), "r"(b1))

__device__ __forceinline__ void split_bf16(float v, __nv_bfloat16& h, __nv_bfloat16& l) {
    h = __float2bfloat16(v);
    l = __float2bfloat16(v - __bfloat162float(h));
}

__device__ __forceinline__ uint32_t bf2_u32(__nv_bfloat16 a, __nv_bfloat16 b) {
    union { __nv_bfloat162 v; uint32_t u; } cvt;
    cvt.v = __halves2bfloat162(a, b);
    return cvt.u;
}

__device__ __forceinline__ void split2_pack(float v0, float v1,
                                            uint32_t& hi, uint32_t& lo) {
    __nv_bfloat16 h0, l0, h1, l1;
    split_bf16(v0, h0, l0);
    split_bf16(v1, h1, l1);
    hi = bf2_u32(h0, h1);
    lo = bf2_u32(l0, l1);
}

__device__ __forceinline__ float ex2(float x) {
    float r;
    asm("ex2.approx.ftz.f32 %0, %1;" : "=f"(r) : "f"(x));
    return r;
}

// ================== weight prep: all weights, one launch ===================
struct WprepP {
    const float* src[6];
    __nv_bfloat16 *dh[6], *dl[6];
};

__global__ __launch_bounds__(256) void wprep_all(WprepP p)
{
    __shared__ float tile[32][33];
    int bid = blockIdx.x;
    int g, layer, kt, nt, Kd, N;
    if (bid < 1536) {
        g = bid / 384; int r = bid % 384;
        layer = r >> 6; int t = r & 63;
        kt = t >> 3; nt = t & 7; Kd = 256; N = 256;
    } else if (bid < 3072) {
        g = 4; int r = bid - 1536;
        layer = r >> 8; int t = r & 255;
        kt = t >> 5; nt = t & 31; Kd = 256; N = 1024;
    } else {
        g = 5; int r = bid - 3072;
        layer = r >> 8; int t = r & 255;
        kt = t >> 3; nt = t & 7; Kd = 1024; N = 256;
    }
    const int k0 = kt << 5, n0 = nt << 5;
    const int tx = threadIdx.x & 31, ty = threadIdx.x >> 5;

    const float* Wp = p.src[g] + (size_t)layer * Kd * N;
#pragma unroll
    for (int r = ty; r < 32; r += 8)
        tile[r][tx] = Wp[(size_t)(k0 + r) * N + n0 + tx];
    __syncthreads();

    __nv_bfloat16* Hp = p.dh[g] + ((size_t)layer * N + n0) * Kd + k0;
    __nv_bfloat16* Lp = p.dl[g] + ((size_t)layer * N + n0) * Kd + k0;
#pragma unroll
    for (int r = ty; r < 32; r += 8) {
        float v = tile[tx][r];
        __nv_bfloat16 h, lo; split_bf16(v, h, lo);
        Hp[(size_t)r * Kd + tx] = h;
        Lp[(size_t)r * Kd + tx] = lo;
    }
}

// ============================ bf16x3 GEMM ==================================
struct GemmP {
    const __nv_bfloat16 *Ah[3], *Al[3], *Wh[3], *Wl[3];
    const float* bias[3];
    float* C[3];
    __nv_bfloat16 *Ch[3], *Cl[3];
};

#define G2_AH 0
#define G2_AL 5120
#define G2_BH 10240
#define G2_BL 20480
#define G2_BUF 30720
#define G2_SMEM (2 * G2_BUF)

__global__ __launch_bounds__(128) void gemm2(GemmP p, int Ncols, int Kd, int mode)
{
    extern __shared__ __align__(16) char smem[];
    const uint32_t sb = smem_u32(smem);

    const int z    = blockIdx.z;
    const __nv_bfloat16* Ah = p.Ah[z];
    const __nv_bfloat16* Al = p.Al[z];
    const __nv_bfloat16* Wh = p.Wh[z];
    const __nv_bfloat16* Wl = p.Wl[z];

    const int tid  = threadIdx.x;
    const int lane = tid & 31;
    const int wn   = tid >> 5;
    const int bm   = blockIdx.y << 6;
    const int bn   = blockIdx.x << 7;

    float acc[4][4][4];
#pragma unroll
    for (int i = 0; i < 4; i++)
#pragma unroll
        for (int j = 0; j < 4; j++)
#pragma unroll
            for (int q = 0; q < 4; q++) acc[i][j][q] = 0.0f;

    const int a_r = lane & 15;
    const int a_c = (lane >> 4) << 3;
    const int b_r = wn * 32 + (lane & 7) + ((lane >> 4) << 3);
    const int b_c = ((lane >> 3) & 1) << 3;

    const int nc = Kd >> 5;

    auto issue = [&](int c, int buf) {
        const uint32_t sa = sb + buf * G2_BUF;
        const size_t kb = (size_t)(c << 5) * 2;
#pragma unroll
        for (int i = 0; i < 2; i++) {
            int s = tid + (i << 7);
            int row = s >> 2, seg = s & 3;
            size_t go = ((size_t)(bm + row) * Kd) * 2 + kb + seg * 16;
            uint32_t so = sa + row * 80 + seg * 16;
            CP16(so + G2_AH, (const char*)Ah + go);
            CP16(so + G2_AL, (const char*)Al + go);
        }
#pragma unroll
        for (int i = 0; i < 4; i++) {
            int s = tid + (i << 7);
            int row = s >> 2, seg = s & 3;
            size_t go = ((size_t)(bn + row) * Kd) * 2 + kb + seg * 16;
            uint32_t so = sa + row * 80 + seg * 16;
            CP16(so + G2_BH, (const char*)Wh + go);
            CP16(so + G2_BL, (const char*)Wl + go);
        }
        CP_COMMIT();
    };

    issue(0, 0);

    for (int c = 0; c < nc; c++) {
        const int buf = c & 1;
        if (c + 1 < nc) { issue(c + 1, buf ^ 1); CP_WAIT1(); }
        else           { CP_WAIT0(); }
        __syncthreads();

        const uint32_t sa = sb + buf * G2_BUF;
#pragma unroll
        for (int ks = 0; ks < 2; ks++) {
            uint32_t ah[4][4], al[4][4];
#pragma unroll
            for (int mb = 0; mb < 4; mb++) {
                uint32_t ao = sa + (uint32_t)(a_r + mb * 16) * 80 + (ks * 16 + a_c) * 2;
                LDSM4(ah[mb], ao + G2_AH);
                LDSM4(al[mb], ao + G2_AL);
            }
            uint32_t bh[2][4], bl[2][4];
#pragma unroll
            for (int np = 0; np < 2; np++) {
                uint32_t bo = sa + (uint32_t)(b_r + np * 16) * 80 + (ks * 16 + b_c) * 2;
                LDSM4(bh[np], bo + G2_BH);
                LDSM4(bl[np], bo + G2_BL);
            }
#pragma unroll
            for (int mb = 0; mb < 4; mb++)
#pragma unroll
                for (int nb = 0; nb < 4; nb++) {
                    const int np = nb >> 1, sl = (nb & 1) << 1;
                    MMA_BF16(acc[mb][nb], ah[mb], bh[np][sl], bh[np][sl + 1]);
                    MMA_BF16(acc[mb][nb], al[mb], bh[np][sl], bh[np][sl + 1]);
                    MMA_BF16(acc[mb][nb], ah[mb], bl[np][sl], bl[np][sl + 1]);
                }
        }
        __syncthreads();
    }

    const float* bias = p.bias[z];
    const int r0 = bm + (lane >> 2);
    const int c0 = bn + wn * 32 + ((lane & 3) << 1);

    if (mode == 2) {
        __nv_bfloat16* Ch = p.Ch[z];
        __nv_bfloat16* Cl = p.Cl[z];
#pragma unroll
        for (int mb = 0; mb < 4; mb++)
#pragma unroll
            for (int nb = 0; nb < 4; nb++) {
                int rr = r0 + mb * 16, cc = c0 + nb * 8;
                float bb0 = bias[cc], bb1 = bias[cc + 1];
#pragma unroll
                for (int hrow = 0; hrow < 2; hrow++) {
                    int r = rr + hrow * 8;
                    float v0 = fmaxf(acc[mb][nb][2 * hrow]     + bb0, 0.0f);
                    float v1 = fmaxf(acc[mb][nb][2 * hrow + 1] + bb1, 0.0f);
                    uint32_t hw, lw;
                    split2_pack(v0, v1, hw, lw);
                    *(uint32_t*)(Ch + (size_t)r * Ncols + cc) = hw;
                    *(uint32_t*)(Cl + (size_t)r * Ncols + cc) = lw;
                }
            }
    } else {    // mode 3: attention QKV layout
        __nv_bfloat16* Ch = p.Ch[z];
        __nv_bfloat16* Cl = p.Cl[z];
#pragma unroll
        for (int mb = 0; mb < 4; mb++)
#pragma unroll
            for (int nb = 0; nb < 4; nb++) {
                int rr = r0 + mb * 16, cc = c0 + nb * 8;
                float bb0 = bias[cc], bb1 = bias[cc + 1];
                int bh = ((rr >> 10) << 3) + (cc >> 5);
                int d  = cc & 31;
#pragma unroll
                for (int hrow = 0; hrow < 2; hrow++) {
                    int r = rr + hrow * 8;
                    int q = r & 1023;
                    float v0 = acc[mb][nb][2 * hrow]     + bb0;
                    float v1 = acc[mb][nb][2 * hrow + 1] + bb1;
                    __nv_bfloat16 h0, l0, h1, l1;
                    split_bf16(v0, h0, l0);
                    split_bf16(v1, h1, l1);
                    if (z < 2) {
                        size_t a = ((size_t)bh * 1024 + q) * 32 + d;
                        *(uint32_t*)(Ch + a) = bf2_u32(h0, h1);
                        *(uint32_t*)(Cl + a) = bf2_u32(l0, l1);
                    } else {
                        // V: hi only (lo term dropped in attention)
                        size_t a = ((size_t)bh * 32 + d) * 1024 + q;
                        Ch[a] = h0; Ch[a + 1024] = h1;
                    }
                }
            }
    }
}

// ================= GEMM + LayerNorm fused (O-proj / FFN2) ==================
// (round-8 256-thread config)
#define GL_AH 0
#define GL_AL 2560
#define GL_BH 5120
#define GL_BL 25600
#define GL_BUF 46080
#define GL_RED   92160
#define GL_BIAS  94208
#define GL_GAM   95232
#define GL_BET   96256
#define GL_SMEM  97280

__global__ __launch_bounds__(256) void gemm_ln(
    const __nv_bfloat16* __restrict__ Ah, const __nv_bfloat16* __restrict__ Al,
    const __nv_bfloat16* __restrict__ Wh, const __nv_bfloat16* __restrict__ Wl,
    const float* __restrict__ bias, const float* __restrict__ gam,
    const float* __restrict__ bet, const float* __restrict__ res,
    float* __restrict__ Xout, __nv_bfloat16* __restrict__ Xh,
    __nv_bfloat16* __restrict__ Xl,
    float* __restrict__ out, const int* __restrict__ il,
    const int* __restrict__ fnum,
    int Kd, int mode)
{
    extern __shared__ __align__(16) char smem[];
    const uint32_t sb = smem_u32(smem);

    const int tid  = threadIdx.x;
    const int lane = tid & 31;
    const int w    = tid >> 5;
    const int bm   = blockIdx.y << 5;

    ((float*)(smem + GL_BIAS))[tid] = bias[tid];
    ((float*)(smem + GL_GAM))[tid]  = gam[tid];
    ((float*)(smem + GL_BET))[tid]  = bet[tid];

    float acc[2][4][4];
#pragma unroll
    for (int i = 0; i < 2; i++)
#pragma unroll
        for (int j = 0; j < 4; j++)
#pragma unroll
            for (int q = 0; q < 4; q++) acc[i][j][q] = 0.0f;

    const int a_r = lane & 15;
    const int a_c = (lane >> 4) << 3;
    const int b_rr = (lane & 7) + ((lane >> 4) << 3);
    const int b_cc = ((lane >> 3) & 1) << 3;

    const int nc = Kd >> 5;

    auto issue = [&](int c, int buf) {
        const uint32_t sa = sb + buf * GL_BUF;
        const size_t kb = (size_t)(c << 5) * 2;
        if (tid < 128) {
            int row = tid >> 2, seg = tid & 3;
            size_t go = ((size_t)(bm + row) * Kd) * 2 + kb + seg * 16;
            uint32_t so = sa + row * 80 + seg * 16;
            CP16(so + GL_AH, (const char*)Ah + go);
            CP16(so + GL_AL, (const char*)Al + go);
        }
#pragma unroll
        for (int i = 0; i < 4; i++) {
            int s = tid + (i << 8);
            int row = s >> 2, seg = s & 3;
            size_t go = ((size_t)row * Kd) * 2 + kb + seg * 16;
            uint32_t so = sa + row * 80 + seg * 16;
            CP16(so + GL_BH, (const char*)Wh + go);
            CP16(so + GL_BL, (const char*)Wl + go);
        }
        CP_COMMIT();
    };

    issue(0, 0);

    for (int c = 0; c < nc; c++) {
        const int buf = c & 1;
        if (c + 1 < nc) { issue(c + 1, buf ^ 1); CP_WAIT1(); }
        else           { CP_WAIT0(); }
        __syncthreads();

        const uint32_t sa = sb + buf * GL_BUF;
#pragma unroll
        for (int ks = 0; ks < 2; ks++) {
            uint32_t ah[2][4], al[2][4];
#pragma unroll
            for (int mb = 0; mb < 2; mb++) {
                uint32_t ao = sa + (uint32_t)(mb * 16 + a_r) * 80 + (ks * 16 + a_c) * 2;
                LDSM4(ah[mb], ao + GL_AH);
                LDSM4(al[mb], ao + GL_AL);
            }
            uint32_t bh[2][4], bl[2][4];
#pragma unroll
            for (int np = 0; np < 2; np++) {
                uint32_t bo = sa + (uint32_t)(w * 32 + np * 16 + b_rr) * 80
                            + (ks * 16 + b_cc) * 2;
                LDSM4(bh[np], bo + GL_BH);
                LDSM4(bl[np], bo + GL_BL);
            }
#pragma unroll
            for (int mb = 0; mb < 2; mb++)
#pragma unroll
                for (int nb = 0; nb < 4; nb++) {
                    const int np = nb >> 1, sl = (nb & 1) << 1;
                    MMA_BF16(acc[mb][nb], ah[mb], bh[np][sl], bh[np][sl + 1]);
                    MMA_BF16(acc[mb][nb], al[mb], bh[np][sl], bh[np][sl + 1]);
                    MMA_BF16(acc[mb][nb], ah[mb], bl[np][sl], bl[np][sl + 1]);
                }
        }
        __syncthreads();
    }

    const float* bias_s = (const float*)(smem + GL_BIAS);
    float2* red = (float2*)(smem + GL_RED);

#pragma unroll
    for (int mb = 0; mb < 2; mb++) {
        float sA = 0.f, qA = 0.f, sB = 0.f, qB = 0.f;
#pragma unroll
        for (int nb = 0; nb < 4; nb++) {
            int cc = w * 32 + nb * 8 + ((lane & 3) << 1);
            int rA = bm + mb * 16 + (lane >> 2);
            int rB = rA + 8;
            float2 resA = *(const float2*)(res + (size_t)rA * Dn + cc);
            float2 resB = *(const float2*)(res + (size_t)rB * Dn + cc);
            float bb0 = bias_s[cc], bb1 = bias_s[cc + 1];
            float v;
            v = acc[mb][nb][0] + bb0 + resA.x; acc[mb][nb][0] = v; sA += v; qA += v * v;
            v = acc[mb][nb][1] + bb1 + resA.y; acc[mb][nb][1] = v; sA += v; qA += v * v;
            v = acc[mb][nb][2] + bb0 + resB.x; acc[mb][nb][2] = v; sB += v; qB += v * v;
            v = acc[mb][nb][3] + bb1 + resB.y; acc[mb][nb][3] = v; sB += v; qB += v * v;
        }
        sA += __shfl_xor_sync(0xffffffffu, sA, 1); qA += __shfl_xor_sync(0xffffffffu, qA, 1);
        sA += __shfl_xor_sync(0xffffffffu, sA, 2); qA += __shfl_xor_sync(0xffffffffu, qA, 2);
        sB += __shfl_xor_sync(0xffffffffu, sB, 1); qB += __shfl_xor_sync(0xffffffffu, qB, 1);
        sB += __shfl_xor_sync(0xffffffffu, sB, 2); qB += __shfl_xor_sync(0xffffffffu, qB, 2);
        if ((lane & 3) == 0) {
            int rlA = mb * 16 + (lane >> 2);
            red[rlA * 8 + w] = make_float2(sA, qA);
            red[(rlA + 8) * 8 + w] = make_float2(sB, qB);
        }
    }
    __syncthreads();

    const float* gam_s = (const float*)(smem + GL_GAM);
    const float* bet_s = (const float*)(smem + GL_BET);
    const int b = bm >> 10;
    int fn = 0;
    if (mode == 2) fn = fnum[b];

#pragma unroll
    for (int mb = 0; mb < 2; mb++) {
#pragma unroll
        for (int hrow = 0; hrow < 2; hrow++) {
            int rl = mb * 16 + hrow * 8 + (lane >> 2);
            int row = bm + rl;
            float su = 0.f, sq = 0.f;
#pragma unroll
            for (int w2 = 0; w2 < 8; w2++) {
                float2 r2 = red[rl * 8 + w2];
                su += r2.x; sq += r2.y;
            }
            float mu = su * (1.0f / Dn);
            float var = sq * (1.0f / Dn) - mu * mu;
            float rs = rsqrtf(var + 1e-5f);

            if (mode == 1) {
#pragma unroll
                for (int nb = 0; nb < 4; nb++) {
                    int cc = w * 32 + nb * 8 + ((lane & 3) << 1);
                    float y0 = (acc[mb][nb][2 * hrow]     - mu) * rs * gam_s[cc]     + bet_s[cc];
                    float y1 = (acc[mb][nb][2 * hrow + 1] - mu) * rs * gam_s[cc + 1] + bet_s[cc + 1];
                    size_t a = (size_t)row * Dn + cc;
                    *(float2*)(Xout + a) = make_float2(y0, y1);
                    uint32_t hw, lw;
                    split2_pack(y0, y1, hw, lw);
                    *(uint32_t*)(Xh + a) = hw;
                    *(uint32_t*)(Xl + a) = lw;
                }
            } else {
                int j = row & 1023;
                if (j < fn) {
                    int idx = il[row];
                    float* op = out + ((size_t)b * NN + idx) * Dn;
#pragma unroll
                    for (int nb = 0; nb < 4; nb++) {
                        int cc = w * 32 + nb * 8 + ((lane & 3) << 1);
                        float y0 = (acc[mb][nb][2 * hrow]     - mu) * rs * gam_s[cc]     + bet_s[cc];
                        float y1 = (acc[mb][nb][2 * hrow + 1] - mu) * rs * gam_s[cc + 1] + bet_s[cc + 1];
                        *(float2*)(op + cc) = make_float2(y0, y1);
                    }
                }
            }
        }
    }
}

// ====================== tensor-core flash attention ========================
// 256 threads, 8 warps x 16 q-rows, 64-key chunks, V hi-only in PV.
#define AT_QH 0
#define AT_QL 10240
#define AT_K  20480             // + buf*10240 : Kh(5120) Kl(5120)
#define AT_V  40960             // + buf*4608  : Vh only
#define AT_SMEM 50176
#define BETA 0.2550165213f      // log2(e)/sqrt(32)

__global__ __launch_bounds__(256, 2) void attn_tc(
    const __nv_bfloat16* __restrict__ Qh, const __nv_bfloat16* __restrict__ Ql,
    const __nv_bfloat16* __restrict__ Kh, const __nv_bfloat16* __restrict__ Kl,
    const __nv_bfloat16* __restrict__ Vh,
    __nv_bfloat16* __restrict__ Oh, __nv_bfloat16* __restrict__ Ol)
{
    extern __shared__ __align__(16) char smem[];
    const uint32_t sb = smem_u32(smem);

    const int tid  = threadIdx.x;
    const int lane = tid & 31;
    const int warp = tid >> 5;
    const int bh   = blockIdx.x;
    const int q0   = blockIdx.y << 7;

    {
        const char* gqh = (const char*)(Qh + ((size_t)bh * 1024 + q0) * 32);
        const char* gql = (const char*)(Ql + ((size_t)bh * 1024 + q0) * 32);
#pragma unroll
        for (int i = 0; i < 2; i++) {
            int s = tid + (i << 8);
            int row = s >> 2, seg = s & 3;
            size_t go = (size_t)row * 64 + seg * 16;
            uint32_t so = (uint32_t)row * 80 + seg * 16;
            CP16(sb + AT_QH + so, gqh + go);
            CP16(sb + AT_QL + so, gql + go);
        }
    }

    auto issueKV = [&](int c, int buf) {
        const int kc = c << 6;
        const uint32_t sk = sb + AT_K + buf * 10240;
        const uint32_t sv = sb + AT_V + buf * 4608;
        {
            const char* gkh = (const char*)(Kh + ((size_t)bh * 1024 + kc) * 32);
            const char* gkl = (const char*)(Kl + ((size_t)bh * 1024 + kc) * 32);
            int row = tid >> 2, seg = tid & 3;
            size_t go = (size_t)row * 64 + seg * 16;
            uint32_t so = (uint32_t)row * 80 + seg * 16;
            CP16(sk + so, gkh + go);
            CP16(sk + 5120 + so, gkl + go);
        }
        {
            const char* gvh = (const char*)(Vh + (size_t)bh * 32 * 1024 + kc);
            int d = tid >> 3, seg = tid & 7;
            size_t go = (size_t)d * 2048 + seg * 16;
            uint32_t so = (uint32_t)d * 144 + seg * 16;
            CP16(sv + so, gvh + go);
        }
        CP_COMMIT();
    };

    issueKV(0, 0);

    float o[4][4];
    float m[2], l[2];
#pragma unroll
    for (int b = 0; b < 4; b++)
#pragma unroll
        for (int q = 0; q < 4; q++) o[b][q] = 0.0f;
    m[0] = m[1] = -1e30f; l[0] = l[1] = 0.0f;

    uint32_t qfh[2][4], qfl[2][4];

    const int a_r = lane & 15;
    const int a_c = (lane >> 4) << 3;
    const int b_rr = (lane & 7) + ((lane >> 4) << 3);
    const int b_cc = ((lane >> 3) & 1) << 3;

    for (int c = 0; c < 16; c++) {
        const int buf = c & 1;
        if (c + 1 < 16) { issueKV(c + 1, buf ^ 1); CP_WAIT1(); }
        else            { CP_WAIT0(); }
        __syncthreads();

        if (c == 0) {
#pragma unroll
            for (int kk = 0; kk < 2; kk++) {
                uint32_t ao = (uint32_t)(warp * 16 + a_r) * 80 + (kk * 16 + a_c) * 2;
                LDSM4(qfh[kk], sb + AT_QH + ao);
                LDSM4(qfl[kk], sb + AT_QL + ao);
            }
        }

        const uint32_t sk = sb + AT_K + buf * 10240;
        const uint32_t sv = sb + AT_V + buf * 4608;

        float s[8][4];
#pragma unroll
        for (int b = 0; b < 8; b++)
#pragma unroll
            for (int q = 0; q < 4; q++) s[b][q] = 0.0f;

#pragma unroll
        for (int g = 0; g < 4; g++) {
            uint32_t kfh[2][4], kfl[2][4];
#pragma unroll
            for (int kk = 0; kk < 2; kk++) {
                uint32_t bo = (uint32_t)(g * 16 + b_rr) * 80 + (kk * 16 + b_cc) * 2;
                LDSM4(kfh[kk], sk + bo);
                LDSM4(kfl[kk], sk + 5120 + bo);
            }
#pragma unroll
            for (int nb = 0; nb < 2; nb++) {
                const int nt = g * 2 + nb, sl = nb << 1;
#pragma unroll
                for (int kk = 0; kk < 2; kk++) {
                    MMA_BF16(s[nt], qfh[kk], kfh[kk][sl], kfh[kk][sl + 1]);
                    MMA_BF16(s[nt], qfl[kk], kfh[kk][sl], kfh[kk][sl + 1]);
                    MMA_BF16(s[nt], qfh[kk], kfl[kk][sl], kfl[kk][sl + 1]);
                }
            }
        }

        float alpha[2], mn2[2];
#pragma unroll
        for (int h = 0; h < 2; h++) {
            float mx = -1e30f;
#pragma unroll
            for (int nt = 0; nt < 8; nt++) {
                mx = fmaxf(mx, s[nt][2 * h]);
                mx = fmaxf(mx, s[nt][2 * h + 1]);
            }
            mx = fmaxf(mx, __shfl_xor_sync(0xffffffffu, mx, 1));
            mx = fmaxf(mx, __shfl_xor_sync(0xffffffffu, mx, 2));
            float mn = fmaxf(m[h], mx);
            alpha[h] = ex2((m[h] - mn) * BETA);
            mn2[h] = mn;
            m[h] = mn;
        }
        {
            float nm0 = mn2[0] * BETA, nm1 = mn2[1] * BETA;
#pragma unroll
            for (int nt = 0; nt < 8; nt++) {
                s[nt][0] = ex2(fmaf(s[nt][0], BETA, -nm0));
                s[nt][1] = ex2(fmaf(s[nt][1], BETA, -nm0));
                s[nt][2] = ex2(fmaf(s[nt][2], BETA, -nm1));
                s[nt][3] = ex2(fmaf(s[nt][3], BETA, -nm1));
            }
        }
#pragma unroll
        for (int h = 0; h < 2; h++) {
            float su = 0.0f;
#pragma unroll
            for (int nt = 0; nt < 8; nt++)
                su += s[nt][2 * h] + s[nt][2 * h + 1];
            su += __shfl_xor_sync(0xffffffffu, su, 1);
            su += __shfl_xor_sync(0xffffffffu, su, 2);
            l[h] = l[h] * alpha[h] + su;
        }
#pragma unroll
        for (int nb = 0; nb < 4; nb++) {
            o[nb][0] *= alpha[0];
            o[nb][1] *= alpha[0];
            o[nb][2] *= alpha[1];
            o[nb][3] *= alpha[1];
        }

        // ---- O += P V (V hi only; P split kept exact) ----
#pragma unroll
        for (int kt = 0; kt < 4; kt++) {
            uint32_t vfh[2][4];
#pragma unroll
            for (int g = 0; g < 2; g++) {
                uint32_t bo = (uint32_t)(g * 16 + b_rr) * 144 + (kt * 16 + b_cc) * 2;
                LDSM4(vfh[g], sv + bo);
            }
            const int t0 = kt * 2, t1 = kt * 2 + 1;
            uint32_t ph[4], pl[4];
            split2_pack(s[t0][0], s[t0][1], ph[0], pl[0]);
            split2_pack(s[t0][2], s[t0][3], ph[1], pl[1]);
            split2_pack(s[t1][0], s[t1][1], ph[2], pl[2]);
            split2_pack(s[t1][2], s[t1][3], ph[3], pl[3]);
#pragma unroll
            for (int nb = 0; nb < 4; nb++) {
                const int g = nb >> 1, sl = (nb & 1) << 1;
                MMA_BF16(o[nb], ph, vfh[g][sl], vfh[g][sl + 1]);
                MMA_BF16(o[nb], pl, vfh[g][sl], vfh[g][sl + 1]);
            }
        }
        __syncthreads();
    }

    const int b  = bh >> 3;
    const int hh = bh & 7;
    {
        float i0 = 1.0f / l[0], i1 = 1.0f / l[1];
#pragma unroll
        for (int h = 0; h < 2; h++) {
            int row = b * 1024 + q0 + warp * 16 + h * 8 + (lane >> 2);
            float inv = h ? i1 : i0;
#pragma unroll
            for (int nb = 0; nb < 4; nb++) {
                int d = nb * 8 + ((lane & 3) << 1);
                float v0 = o[nb][2 * h]     * inv;
                float v1 = o[nb][2 * h + 1] * inv;
                uint32_t hw, lw;
                split2_pack(v0, v1, hw, lw);
                size_t a = (size_t)row * Dn + hh * 32 + d;
                *(uint32_t*)(Oh + a) = hw;
                *(uint32_t*)(Ol + a) = lw;
            }
        }
    }
}

// ---------------------------------------------------------------------------
// Gather + MCSP
// ---------------------------------------------------------------------------
__global__ __launch_bounds__(256) void gather_cls_kernel(
    const float* __restrict__ out, const float* __restrict__ qpos,
    const float* __restrict__ fgs, const int* __restrict__ il,
    const float* __restrict__ Wcls, const float* __restrict__ bcls,
    float* __restrict__ tgt,
    __nv_bfloat16* __restrict__ tgh, __nv_bfloat16* __restrict__ tgl,
    __nv_bfloat16* __restrict__ qkh, __nv_bfloat16* __restrict__ qkl)
{
    __shared__ float qs[Dn];
    __shared__ float sc[16];

    int row = blockIdx.x;
    int b   = row >> 10;
    int t   = threadIdx.x;
    int lane = t & 31, w = t >> 5;
    int idx = il[row];
    size_t src = ((size_t)b * NN + idx) * Dn + t;
    float qv = out[src];
    qs[t] = qv;
    __syncthreads();

#pragma unroll
    for (int ci = 0; ci < 2; ci++) {
        int c = w + ci * 8;
        if (c < NCLSn) {
            float sum = 0.0f;
#pragma unroll
            for (int j = 0; j < 8; j++) {
                int e = lane + (j << 5);
                sum += qs[e] * Wcls[e * NCLSn + c];
            }
#pragma unroll
            for (int o = 16; o; o >>= 1) sum += __shfl_down_sync(0xffffffffu, sum, o);
            if (lane == 0) sc[c] = sum + bcls[c];
        }
    }
    __syncthreads();

    float mx = sc[0];
#pragma unroll
    for (int c = 1; c < NCLSn; c++) mx = fmaxf(mx, sc[c]);
    float mc = (1.0f / (1.0f + __expf(-mx))) * fgs[(size_t)b * NN + idx];

    float tv = tgt[(size_t)row * Dn + t] = qv * mc;
    float qk = tv + qpos[src];
    size_t i = (size_t)row * Dn + t;
    __nv_bfloat16 h, lo;
    split_bf16(tv, h, lo); tgh[i] = h; tgl[i] = lo;
    split_bf16(qk, h, lo); qkh[i] = h; qkl[i] = lo;
}

// ---------------------------------------------------------------------------
// Host-side orchestration
// ---------------------------------------------------------------------------
extern "C" void kernel_launch(void* const* d_in, const int* in_sizes, int n_in,
                              void* d_out, int out_size)
{
    int qp_idx = (in_sizes[1] == 8) ? 4 : 1;

    const float* query = (const float*)d_in[0];
    const float* qpos  = (const float*)d_in[qp_idx];
    const float* fgs   = (const float*)d_in[6];
    const int*   fnum  = (const int*)d_in[7];
    const int*   inds  = (const int*)d_in[8];
    const float* Wq = (const float*)d_in[9],  *bq = (const float*)d_in[10];
    const float* Wk = (const float*)d_in[11], *bk = (const float*)d_in[12];
    const float* Wv = (const float*)d_in[13], *bv = (const float*)d_in[14];
    const float* Wo = (const float*)d_in[15], *bo = (const float*)d_in[16];
    const float* g1 = (const float*)d_in[17], *be1 = (const float*)d_in[18];
    const float* W1 = (const float*)d_in[19], *b1 = (const float*)d_in[20];
    const float* W2 = (const float*)d_in[21], *b2 = (const float*)d_in[22];
    const float* g2 = (const float*)d_in[23], *be2 = (const float*)d_in[24];
    const float* Wcls = (const float*)d_in[25], *bcls = (const float*)d_in[26];

    float* out = (float*)d_out;

    unsigned char* base = nullptr;
    cudaGetSymbolAddress((void**)&base, g_mem);
#define FP(off)  ((float*)(base + (off)))
#define BF(off)  ((__nv_bfloat16*)(base + (off)))

    float *tgt = FP(OF_TGT), *Xb = FP(OF_XB);
    __nv_bfloat16 *qkh = BF(OF_QKH), *qkl = BF(OF_QKL);
    __nv_bfloat16 *tgh = BF(OF_TGH), *tgl = BF(OF_TGL);
    __nv_bfloat16 *qh  = BF(OF_QH),  *ql  = BF(OF_QL);
    __nv_bfloat16 *kh  = BF(OF_KH),  *kl  = BF(OF_KL);
    __nv_bfloat16 *vh  = BF(OF_VH),  *vl  = BF(OF_VL);
    __nv_bfloat16 *ath = BF(OF_ATH), *atl = BF(OF_ATL);
    __nv_bfloat16 *xh  = BF(OF_XH),  *xl  = BF(OF_XL);
    __nv_bfloat16 *hh  = BF(OF_HH),  *hl  = BF(OF_HL);
    __nv_bfloat16 *wqh = BF(OF_WQH), *wql = BF(OF_WQL);
    __nv_bfloat16 *wkh = BF(OF_WKH), *wkl = BF(OF_WKL);
    __nv_bfloat16 *wvh = BF(OF_WVH), *wvl = BF(OF_WVL);
    __nv_bfloat16 *woh = BF(OF_WOH), *wol = BF(OF_WOL);
    __nv_bfloat16 *w1h = BF(OF_W1H), *w1l = BF(OF_W1L);
    __nv_bfloat16 *w2h = BF(OF_W2H), *w2l = BF(OF_W2L);

    cudaFuncSetAttribute(gemm2, cudaFuncAttributeMaxDynamicSharedMemorySize, G2_SMEM);
    cudaFuncSetAttribute(gemm_ln, cudaFuncAttributeMaxDynamicSharedMemorySize, GL_SMEM);
    cudaFuncSetAttribute(attn_tc, cudaFuncAttributeMaxDynamicSharedMemorySize, AT_SMEM);

    {
        WprepP wp{};
        wp.src[0] = Wq; wp.dh[0] = wqh; wp.dl[0] = wql;
        wp.src[1] = Wk; wp.dh[1] = wkh; wp.dl[1] = wkl;
        wp.src[2] = Wv; wp.dh[2] = wvh; wp.dl[2] = wvl;
        wp.src[3] = Wo; wp.dh[3] = woh; wp.dl[3] = wol;
        wp.src[4] = W1; wp.dh[4] = w1h; wp.dl[4] = w1l;
        wp.src[5] = W2; wp.dh[5] = w2h; wp.dl[5] = w2l;
        wprep_all<<<4608, 256>>>(wp);
    }

    cudaMemcpyAsync(out, query, sizeof(float) * (size_t)Bn * NN * Dn,
                    cudaMemcpyDeviceToDevice);

    for (int l = 0; l < L_LAYERS; l++) {
        const int* il = inds + (size_t)l * ROWS;
        const size_t wd = (size_t)l * Dn * Dn;
        const size_t wf = (size_t)l * Dn * FFNn;

        gather_cls_kernel<<<ROWS, 256>>>(out, qpos, fgs, il, Wcls, bcls,
                                         tgt, tgh, tgl, qkh, qkl);

        {   // QKV batched -> head layouts (V: hi only)
            GemmP p{};
            p.Ah[0] = qkh; p.Al[0] = qkl; p.Wh[0] = wqh + wd; p.Wl[0] = wql + wd;
            p.bias[0] = bq + l * Dn; p.Ch[0] = qh; p.Cl[0] = ql;
            p.Ah[1] = qkh; p.Al[1] = qkl; p.Wh[1] = wkh + wd; p.Wl[1] = wkl + wd;
            p.bias[1] = bk + l * Dn; p.Ch[1] = kh; p.Cl[1] = kl;
            p.Ah[2] = tgh; p.Al[2] = tgl; p.Wh[2] = wvh + wd; p.Wl[2] = wvl + wd;
            p.bias[2] = bv + l * Dn; p.Ch[2] = vh; p.Cl[2] = vl;
            gemm2<<<dim3(2, 64, 3), 128, G2_SMEM>>>(p, Dn, Dn, 3);
        }

        attn_tc<<<dim3(Bn * Hn, Kn / 128), 256, AT_SMEM>>>(qh, ql, kh, kl, vh,
                                                           ath, atl);

        // O projection + LN1 fused (res = tgt) -> Xb, xh, xl
        gemm_ln<<<dim3(1, ROWS / 32), 256, GL_SMEM>>>(
            ath, atl, woh + wd, wol + wd,
            bo + l * Dn, g1 + l * Dn, be1 + l * Dn, tgt,
            Xb, xh, xl, nullptr, nullptr, nullptr, Dn, 1);

        {   // FFN1 (relu, bf16 split out)
            GemmP p{};
            p.Ah[0] = xh; p.Al[0] = xl; p.Wh[0] = w1h + wf; p.Wl[0] = w1l + wf;
            p.bias[0] = b1 + l * FFNn; p.Ch[0] = hh; p.Cl[0] = hl;
            gemm2<<<dim3(8, 64, 1), 128, G2_SMEM>>>(p, FFNn, Dn, 2);
        }

        // FFN2 + LN2 + ragged scatter fused (res = Xb) -> out
        gemm_ln<<<dim3(1, ROWS / 32), 256, GL_SMEM>>>(
            hh, hl, w2h + wf, w2l + wf,
            b2 + l * Dn, g2 + l * Dn, be2 + l * Dn, Xb,
            nullptr, nullptr, nullptr, out, il, fnum, FFNn, 2);
    }
}

// round 11
// speedup vs baseline: 1.3761x; 1.2789x over previous
#include <cuda_runtime.h>
#include <cuda_bf16.h>
#include <cstdint>

// ---------------------------------------------------------------------------
// Focus-DETR encoder — round 11: B operand bf16-rounded in EVERY matmul
// (A stays hi+lo split). 2-term GEMMs, halved weight streams.
// ---------------------------------------------------------------------------

#define L_LAYERS 6
#define Bn 4
#define NN 23890
#define Kn 1024
#define Dn 256
#define Hn 8
#define HDn 32
#define FFNn 1024
#define NCLSn 15

#define ROWS (Bn * Kn)          // 4096
#define RD   (ROWS * Dn)        // 1048576 elements

// ---------------- scratch carving ----------------
constexpr size_t SZ_F  = (size_t)RD * 4;
constexpr size_t SZ_B  = (size_t)RD * 2;
constexpr size_t SZ_H  = (size_t)ROWS * FFNn * 2;
constexpr size_t SZ_WD = (size_t)L_LAYERS * Dn * Dn * 2;
constexpr size_t SZ_W1 = (size_t)L_LAYERS * Dn * FFNn * 2;

constexpr size_t OF_TGT = 0;
constexpr size_t OF_XB  = OF_TGT + SZ_F;
constexpr size_t OF_QKH = OF_XB  + SZ_F;
constexpr size_t OF_QKL = OF_QKH + SZ_B;
constexpr size_t OF_TGH = OF_QKL + SZ_B;
constexpr size_t OF_TGL = OF_TGH + SZ_B;
constexpr size_t OF_QH  = OF_TGL + SZ_B;
constexpr size_t OF_QL  = OF_QH  + SZ_B;
constexpr size_t OF_KH  = OF_QL  + SZ_B;
constexpr size_t OF_VH  = OF_KH  + SZ_B;
constexpr size_t OF_ATH = OF_VH  + SZ_B;
constexpr size_t OF_ATL = OF_ATH + SZ_B;
constexpr size_t OF_XH  = OF_ATL + SZ_B;
constexpr size_t OF_XL  = OF_XH  + SZ_B;
constexpr size_t OF_HH  = OF_XL  + SZ_B;
constexpr size_t OF_HL  = OF_HH  + SZ_H;
constexpr size_t OF_WQH = OF_HL  + SZ_H;
constexpr size_t OF_WKH = OF_WQH + SZ_WD;
constexpr size_t OF_WVH = OF_WKH + SZ_WD;
constexpr size_t OF_WOH = OF_WVH + SZ_WD;
constexpr size_t OF_W1H = OF_WOH + SZ_WD;
constexpr size_t OF_W2H = OF_W1H + SZ_W1;
constexpr size_t G_TOTAL = OF_W2H + SZ_W1;

__device__ __align__(1024) unsigned char g_mem[G_TOTAL];

// ============================ PTX helpers ==================================

__device__ __forceinline__ uint32_t smem_u32(const void* p) {
    uint32_t a;
    asm("{ .reg .u64 t; cvta.to.shared.u64 t, %1; cvt.u32.u64 %0, t; }"
        : "=r"(a) : "l"(p));
    return a;
}

#define CP16(sa, ga)                                                            \
    asm volatile("cp.async.ca.shared.global [%0], [%1], 16;"                    \
                 :: "r"(sa), "l"(__cvta_generic_to_global(ga)))
#define CP_COMMIT() asm volatile("cp.async.commit_group;" ::: "memory")
#define CP_WAIT0()  asm volatile("cp.async.wait_group 0;" ::: "memory")
#define CP_WAIT1()  asm volatile("cp.async.wait_group 1;" ::: "memory")

#define LDSM4(r, addr)                                                          \
    asm volatile("ldmatrix.sync.aligned.m8n8.x4.shared.b16 {%0,%1,%2,%3}, [%4];"\
        : "=r"((r)[0]), "=r"((r)[1]), "=r"((r)[2]), "=r"((r)[3]) : "r"(addr))

#define MMA_BF16(d, a, b0, b1)                                                  \
    asm volatile("mma.sync.aligned.m16n8k16.row.col.f32.bf16.bf16.f32 "         \
        "{%0,%1,%2,%3}, {%4,%5,%6,%7}, {%8,%9}, {%0,%1,%2,%3};"                 \
        : "+f"((d)[0]), "+f"((d)[1]), "+f"((d)[2]), "+f"((d)[3])                \
        : "r"((a)[0]), "r"((a)[1]), "r"((a)[2]), "r"((a)[3]), "r"(b0), "r"(b1))

__device__ __forceinline__ void split_bf16(float v, __nv_bfloat16& h, __nv_bfloat16& l) {
    h = __float2bfloat16(v);
    l = __float2bfloat16(v - __bfloat162float(h));
}

__device__ __forceinline__ uint32_t bf2_u32(__nv_bfloat16 a, __nv_bfloat16 b) {
    union { __nv_bfloat162 v; uint32_t u; } cvt;
    cvt.v = __halves2bfloat162(a, b);
    return cvt.u;
}

__device__ __forceinline__ void split2_pack(float v0, float v1,
                                            uint32_t& hi, uint32_t& lo) {
    __nv_bfloat16 h0, l0, h1, l1;
    split_bf16(v0, h0, l0);
    split_bf16(v1, h1, l1);
    hi = bf2_u32(h0, h1);
    lo = bf2_u32(l0, l1);
}

__device__ __forceinline__ float ex2(float x) {
    float r;
    asm("ex2.approx.ftz.f32 %0, %1;" : "=f"(r) : "f"(x));
    return r;
}

// ================== weight prep: all weights (hi only) =====================
struct WprepP {
    const float* src[6];
    __nv_bfloat16* dh[6];
};

__global__ __launch_bounds__(256) void wprep_all(WprepP p)
{
    __shared__ float tile[32][33];
    int bid = blockIdx.x;
    int g, layer, kt, nt, Kd, N;
    if (bid < 1536) {
        g = bid / 384; int r = bid % 384;
        layer = r >> 6; int t = r & 63;
        kt = t >> 3; nt = t & 7; Kd = 256; N = 256;
    } else if (bid < 3072) {
        g = 4; int r = bid - 1536;
        layer = r >> 8; int t = r & 255;
        kt = t >> 5; nt = t & 31; Kd = 256; N = 1024;
    } else {
        g = 5; int r = bid - 3072;
        layer = r >> 8; int t = r & 255;
        kt = t >> 3; nt = t & 7; Kd = 1024; N = 256;
    }
    const int k0 = kt << 5, n0 = nt << 5;
    const int tx = threadIdx.x & 31, ty = threadIdx.x >> 5;

    const float* Wp = p.src[g] + (size_t)layer * Kd * N;
#pragma unroll
    for (int r = ty; r < 32; r += 8)
        tile[r][tx] = Wp[(size_t)(k0 + r) * N + n0 + tx];
    __syncthreads();

    __nv_bfloat16* Hp = p.dh[g] + ((size_t)layer * N + n0) * Kd + k0;
#pragma unroll
    for (int r = ty; r < 32; r += 8)
        Hp[(size_t)r * Kd + tx] = __float2bfloat16(tile[tx][r]);
}

// ===================== bf16 GEMM (A split, B rounded) ======================
// C = (Ah+Al) @ Bh^T : 2 mma terms.
struct GemmP {
    const __nv_bfloat16 *Ah[3], *Al[3], *Wh[3];
    const float* bias[3];
    __nv_bfloat16 *Ch[3], *Cl[3];
};

#define G2_AH 0
#define G2_AL 5120
#define G2_BH 10240
#define G2_BUF 20480
#define G2_SMEM (2 * G2_BUF)

__global__ __launch_bounds__(128) void gemm2(GemmP p, int Ncols, int Kd, int mode)
{
    extern __shared__ __align__(16) char smem[];
    const uint32_t sb = smem_u32(smem);

    const int z    = blockIdx.z;
    const __nv_bfloat16* Ah = p.Ah[z];
    const __nv_bfloat16* Al = p.Al[z];
    const __nv_bfloat16* Wh = p.Wh[z];

    const int tid  = threadIdx.x;
    const int lane = tid & 31;
    const int wn   = tid >> 5;
    const int bm   = blockIdx.y << 6;
    const int bn   = blockIdx.x << 7;

    float acc[4][4][4];
#pragma unroll
    for (int i = 0; i < 4; i++)
#pragma unroll
        for (int j = 0; j < 4; j++)
#pragma unroll
            for (int q = 0; q < 4; q++) acc[i][j][q] = 0.0f;

    const int a_r = lane & 15;
    const int a_c = (lane >> 4) << 3;
    const int b_r = wn * 32 + (lane & 7) + ((lane >> 4) << 3);
    const int b_c = ((lane >> 3) & 1) << 3;

    const int nc = Kd >> 5;

    auto issue = [&](int c, int buf) {
        const uint32_t sa = sb + buf * G2_BUF;
        const size_t kb = (size_t)(c << 5) * 2;
#pragma unroll
        for (int i = 0; i < 2; i++) {           // A: 64 rows x 4 segs, hi+lo
            int s = tid + (i << 7);
            int row = s >> 2, seg = s & 3;
            size_t go = ((size_t)(bm + row) * Kd) * 2 + kb + seg * 16;
            uint32_t so = sa + row * 80 + seg * 16;
            CP16(so + G2_AH, (const char*)Ah + go);
            CP16(so + G2_AL, (const char*)Al + go);
        }
#pragma unroll
        for (int i = 0; i < 4; i++) {           // B: 128 rows x 4 segs, hi only
            int s = tid + (i << 7);
            int row = s >> 2, seg = s & 3;
            size_t go = ((size_t)(bn + row) * Kd) * 2 + kb + seg * 16;
            uint32_t so = sa + row * 80 + seg * 16;
            CP16(so + G2_BH, (const char*)Wh + go);
        }
        CP_COMMIT();
    };

    issue(0, 0);

    for (int c = 0; c < nc; c++) {
        const int buf = c & 1;
        if (c + 1 < nc) { issue(c + 1, buf ^ 1); CP_WAIT1(); }
        else           { CP_WAIT0(); }
        __syncthreads();

        const uint32_t sa = sb + buf * G2_BUF;
#pragma unroll
        for (int ks = 0; ks < 2; ks++) {
            uint32_t ah[4][4], al[4][4];
#pragma unroll
            for (int mb = 0; mb < 4; mb++) {
                uint32_t ao = sa + (uint32_t)(a_r + mb * 16) * 80 + (ks * 16 + a_c) * 2;
                LDSM4(ah[mb], ao + G2_AH);
                LDSM4(al[mb], ao + G2_AL);
            }
            uint32_t bh[2][4];
#pragma unroll
            for (int np = 0; np < 2; np++) {
                uint32_t bo = sa + (uint32_t)(b_r + np * 16) * 80 + (ks * 16 + b_c) * 2;
                LDSM4(bh[np], bo + G2_BH);
            }
#pragma unroll
            for (int mb = 0; mb < 4; mb++)
#pragma unroll
                for (int nb = 0; nb < 4; nb++) {
                    const int np = nb >> 1, sl = (nb & 1) << 1;
                    MMA_BF16(acc[mb][nb], ah[mb], bh[np][sl], bh[np][sl + 1]);
                    MMA_BF16(acc[mb][nb], al[mb], bh[np][sl], bh[np][sl + 1]);
                }
        }
        __syncthreads();
    }

    const float* bias = p.bias[z];
    const int r0 = bm + (lane >> 2);
    const int c0 = bn + wn * 32 + ((lane & 3) << 1);

    if (mode == 2) {   // FFN1: relu + split out (h is A of FFN2)
        __nv_bfloat16* Ch = p.Ch[z];
        __nv_bfloat16* Cl = p.Cl[z];
#pragma unroll
        for (int mb = 0; mb < 4; mb++)
#pragma unroll
            for (int nb = 0; nb < 4; nb++) {
                int rr = r0 + mb * 16, cc = c0 + nb * 8;
                float bb0 = bias[cc], bb1 = bias[cc + 1];
#pragma unroll
                for (int hrow = 0; hrow < 2; hrow++) {
                    int r = rr + hrow * 8;
                    float v0 = fmaxf(acc[mb][nb][2 * hrow]     + bb0, 0.0f);
                    float v1 = fmaxf(acc[mb][nb][2 * hrow + 1] + bb1, 0.0f);
                    uint32_t hw, lw;
                    split2_pack(v0, v1, hw, lw);
                    *(uint32_t*)(Ch + (size_t)r * Ncols + cc) = hw;
                    *(uint32_t*)(Cl + (size_t)r * Ncols + cc) = lw;
                }
            }
    } else {           // mode 3: attention QKV layout
        __nv_bfloat16* Ch = p.Ch[z];
        __nv_bfloat16* Cl = p.Cl[z];
#pragma unroll
        for (int mb = 0; mb < 4; mb++)
#pragma unroll
            for (int nb = 0; nb < 4; nb++) {
                int rr = r0 + mb * 16, cc = c0 + nb * 8;
                float bb0 = bias[cc], bb1 = bias[cc + 1];
                int bh = ((rr >> 10) << 3) + (cc >> 5);
                int d  = cc & 31;
#pragma unroll
                for (int hrow = 0; hrow < 2; hrow++) {
                    int r = rr + hrow * 8;
                    int q = r & 1023;
                    float v0 = acc[mb][nb][2 * hrow]     + bb0;
                    float v1 = acc[mb][nb][2 * hrow + 1] + bb1;
                    __nv_bfloat16 h0, l0, h1, l1;
                    split_bf16(v0, h0, l0);
                    split_bf16(v1, h1, l1);
                    if (z == 0) {          // Q: split (A of S-mma)
                        size_t a = ((size_t)bh * 1024 + q) * 32 + d;
                        *(uint32_t*)(Ch + a) = bf2_u32(h0, h1);
                        *(uint32_t*)(Cl + a) = bf2_u32(l0, l1);
                    } else if (z == 1) {   // K: hi only (B of S-mma)
                        size_t a = ((size_t)bh * 1024 + q) * 32 + d;
                        *(uint32_t*)(Ch + a) = bf2_u32(h0, h1);
                    } else {               // V: transposed, hi only
                        size_t a = ((size_t)bh * 32 + d) * 1024 + q;
                        Ch[a] = h0; Ch[a + 1024] = h1;
                    }
                }
            }
    }
}

// ================= GEMM + LayerNorm fused (O-proj / FFN2) ==================
// 256 threads, tile 32x256, A split + B rounded (2 mma terms).
#define GL_AH 0
#define GL_AL 2560
#define GL_BH 5120
#define GL_BUF 25600
#define GL_RED   51200
#define GL_BIAS  53248
#define GL_GAM   54272
#define GL_BET   55296
#define GL_SMEM  56320

__global__ __launch_bounds__(256) void gemm_ln(
    const __nv_bfloat16* __restrict__ Ah, const __nv_bfloat16* __restrict__ Al,
    const __nv_bfloat16* __restrict__ Wh,
    const float* __restrict__ bias, const float* __restrict__ gam,
    const float* __restrict__ bet, const float* __restrict__ res,
    float* __restrict__ Xout, __nv_bfloat16* __restrict__ Xh,
    __nv_bfloat16* __restrict__ Xl,
    float* __restrict__ out, const int* __restrict__ il,
    const int* __restrict__ fnum,
    int Kd, int mode)
{
    extern __shared__ __align__(16) char smem[];
    const uint32_t sb = smem_u32(smem);

    const int tid  = threadIdx.x;
    const int lane = tid & 31;
    const int w    = tid >> 5;
    const int bm   = blockIdx.y << 5;

    ((float*)(smem + GL_BIAS))[tid] = bias[tid];
    ((float*)(smem + GL_GAM))[tid]  = gam[tid];
    ((float*)(smem + GL_BET))[tid]  = bet[tid];

    float acc[2][4][4];
#pragma unroll
    for (int i = 0; i < 2; i++)
#pragma unroll
        for (int j = 0; j < 4; j++)
#pragma unroll
            for (int q = 0; q < 4; q++) acc[i][j][q] = 0.0f;

    const int a_r = lane & 15;
    const int a_c = (lane >> 4) << 3;
    const int b_rr = (lane & 7) + ((lane >> 4) << 3);
    const int b_cc = ((lane >> 3) & 1) << 3;

    const int nc = Kd >> 5;

    auto issue = [&](int c, int buf) {
        const uint32_t sa = sb + buf * GL_BUF;
        const size_t kb = (size_t)(c << 5) * 2;
        if (tid < 128) {                       // A: 32 rows x 4 segs, hi+lo
            int row = tid >> 2, seg = tid & 3;
            size_t go = ((size_t)(bm + row) * Kd) * 2 + kb + seg * 16;
            uint32_t so = sa + row * 80 + seg * 16;
            CP16(so + GL_AH, (const char*)Ah + go);
            CP16(so + GL_AL, (const char*)Al + go);
        }
#pragma unroll
        for (int i = 0; i < 4; i++) {          // B: 256 rows x 4 segs, hi only
            int s = tid + (i << 8);
            int row = s >> 2, seg = s & 3;
            size_t go = ((size_t)row * Kd) * 2 + kb + seg * 16;
            uint32_t so = sa + row * 80 + seg * 16;
            CP16(so + GL_BH, (const char*)Wh + go);
        }
        CP_COMMIT();
    };

    issue(0, 0);

    for (int c = 0; c < nc; c++) {
        const int buf = c & 1;
        if (c + 1 < nc) { issue(c + 1, buf ^ 1); CP_WAIT1(); }
        else           { CP_WAIT0(); }
        __syncthreads();

        const uint32_t sa = sb + buf * GL_BUF;
#pragma unroll
        for (int ks = 0; ks < 2; ks++) {
            uint32_t ah[2][4], al[2][4];
#pragma unroll
            for (int mb = 0; mb < 2; mb++) {
                uint32_t ao = sa + (uint32_t)(mb * 16 + a_r) * 80 + (ks * 16 + a_c) * 2;
                LDSM4(ah[mb], ao + GL_AH);
                LDSM4(al[mb], ao + GL_AL);
            }
            uint32_t bh[2][4];
#pragma unroll
            for (int np = 0; np < 2; np++) {
                uint32_t bo = sa + (uint32_t)(w * 32 + np * 16 + b_rr) * 80
                            + (ks * 16 + b_cc) * 2;
                LDSM4(bh[np], bo + GL_BH);
            }
#pragma unroll
            for (int mb = 0; mb < 2; mb++)
#pragma unroll
                for (int nb = 0; nb < 4; nb++) {
                    const int np = nb >> 1, sl = (nb & 1) << 1;
                    MMA_BF16(acc[mb][nb], ah[mb], bh[np][sl], bh[np][sl + 1]);
                    MMA_BF16(acc[mb][nb], al[mb], bh[np][sl], bh[np][sl + 1]);
                }
        }
        __syncthreads();
    }

    const float* bias_s = (const float*)(smem + GL_BIAS);
    float2* red = (float2*)(smem + GL_RED);

#pragma unroll
    for (int mb = 0; mb < 2; mb++) {
        float sA = 0.f, qA = 0.f, sB = 0.f, qB = 0.f;
#pragma unroll
        for (int nb = 0; nb < 4; nb++) {
            int cc = w * 32 + nb * 8 + ((lane & 3) << 1);
            int rA = bm + mb * 16 + (lane >> 2);
            int rB = rA + 8;
            float2 resA = *(const float2*)(res + (size_t)rA * Dn + cc);
            float2 resB = *(const float2*)(res + (size_t)rB * Dn + cc);
            float bb0 = bias_s[cc], bb1 = bias_s[cc + 1];
            float v;
            v = acc[mb][nb][0] + bb0 + resA.x; acc[mb][nb][0] = v; sA += v; qA += v * v;
            v = acc[mb][nb][1] + bb1 + resA.y; acc[mb][nb][1] = v; sA += v; qA += v * v;
            v = acc[mb][nb][2] + bb0 + resB.x; acc[mb][nb][2] = v; sB += v; qB += v * v;
            v = acc[mb][nb][3] + bb1 + resB.y; acc[mb][nb][3] = v; sB += v; qB += v * v;
        }
        sA += __shfl_xor_sync(0xffffffffu, sA, 1); qA += __shfl_xor_sync(0xffffffffu, qA, 1);
        sA += __shfl_xor_sync(0xffffffffu, sA, 2); qA += __shfl_xor_sync(0xffffffffu, qA, 2);
        sB += __shfl_xor_sync(0xffffffffu, sB, 1); qB += __shfl_xor_sync(0xffffffffu, qB, 1);
        sB += __shfl_xor_sync(0xffffffffu, sB, 2); qB += __shfl_xor_sync(0xffffffffu, qB, 2);
        if ((lane & 3) == 0) {
            int rlA = mb * 16 + (lane >> 2);
            red[rlA * 8 + w] = make_float2(sA, qA);
            red[(rlA + 8) * 8 + w] = make_float2(sB, qB);
        }
    }
    __syncthreads();

    const float* gam_s = (const float*)(smem + GL_GAM);
    const float* bet_s = (const float*)(smem + GL_BET);
    const int b = bm >> 10;
    int fn = 0;
    if (mode == 2) fn = fnum[b];

#pragma unroll
    for (int mb = 0; mb < 2; mb++) {
#pragma unroll
        for (int hrow = 0; hrow < 2; hrow++) {
            int rl = mb * 16 + hrow * 8 + (lane >> 2);
            int row = bm + rl;
            float su = 0.f, sq = 0.f;
#pragma unroll
            for (int w2 = 0; w2 < 8; w2++) {
                float2 r2 = red[rl * 8 + w2];
                su += r2.x; sq += r2.y;
            }
            float mu = su * (1.0f / Dn);
            float var = sq * (1.0f / Dn) - mu * mu;
            float rs = rsqrtf(var + 1e-5f);

            if (mode == 1) {
#pragma unroll
                for (int nb = 0; nb < 4; nb++) {
                    int cc = w * 32 + nb * 8 + ((lane & 3) << 1);
                    float y0 = (acc[mb][nb][2 * hrow]     - mu) * rs * gam_s[cc]     + bet_s[cc];
                    float y1 = (acc[mb][nb][2 * hrow + 1] - mu) * rs * gam_s[cc + 1] + bet_s[cc + 1];
                    size_t a = (size_t)row * Dn + cc;
                    *(float2*)(Xout + a) = make_float2(y0, y1);
                    uint32_t hw, lw;
                    split2_pack(y0, y1, hw, lw);
                    *(uint32_t*)(Xh + a) = hw;
                    *(uint32_t*)(Xl + a) = lw;
                }
            } else {
                int j = row & 1023;
                if (j < fn) {
                    int idx = il[row];
                    float* op = out + ((size_t)b * NN + idx) * Dn;
#pragma unroll
                    for (int nb = 0; nb < 4; nb++) {
                        int cc = w * 32 + nb * 8 + ((lane & 3) << 1);
                        float y0 = (acc[mb][nb][2 * hrow]     - mu) * rs * gam_s[cc]     + bet_s[cc];
                        float y1 = (acc[mb][nb][2 * hrow + 1] - mu) * rs * gam_s[cc + 1] + bet_s[cc + 1];
                        *(float2*)(op + cc) = make_float2(y0, y1);
                    }
                }
            }
        }
    }
}

// ====================== tensor-core flash attention ========================
// 256 threads, 8 warps x 16 q-rows, 64-key chunks.
// S = (Qh+Ql)·Kh ; O += (Ph+Pl)·Vh.
#define AT_QH 0
#define AT_QL 10240
#define AT_K  20480             // + buf*5120 : Kh only
#define AT_V  30720             // + buf*4608 : Vh only
#define AT_SMEM 39936
#define BETA 0.2550165213f      // log2(e)/sqrt(32)

__global__ __launch_bounds__(256, 2) void attn_tc(
    const __nv_bfloat16* __restrict__ Qh, const __nv_bfloat16* __restrict__ Ql,
    const __nv_bfloat16* __restrict__ Kh, const __nv_bfloat16* __restrict__ Vh,
    __nv_bfloat16* __restrict__ Oh, __nv_bfloat16* __restrict__ Ol)
{
    extern __shared__ __align__(16) char smem[];
    const uint32_t sb = smem_u32(smem);

    const int tid  = threadIdx.x;
    const int lane = tid & 31;
    const int warp = tid >> 5;
    const int bh   = blockIdx.x;
    const int q0   = blockIdx.y << 7;

    {
        const char* gqh = (const char*)(Qh + ((size_t)bh * 1024 + q0) * 32);
        const char* gql = (const char*)(Ql + ((size_t)bh * 1024 + q0) * 32);
#pragma unroll
        for (int i = 0; i < 2; i++) {
            int s = tid + (i << 8);
            int row = s >> 2, seg = s & 3;
            size_t go = (size_t)row * 64 + seg * 16;
            uint32_t so = (uint32_t)row * 80 + seg * 16;
            CP16(sb + AT_QH + so, gqh + go);
            CP16(sb + AT_QL + so, gql + go);
        }
    }

    auto issueKV = [&](int c, int buf) {
        const int kc = c << 6;
        const uint32_t sk = sb + AT_K + buf * 5120;
        const uint32_t sv = sb + AT_V + buf * 4608;
        {
            const char* gkh = (const char*)(Kh + ((size_t)bh * 1024 + kc) * 32);
            int row = tid >> 2, seg = tid & 3;
            size_t go = (size_t)row * 64 + seg * 16;
            uint32_t so = (uint32_t)row * 80 + seg * 16;
            CP16(sk + so, gkh + go);
        }
        {
            const char* gvh = (const char*)(Vh + (size_t)bh * 32 * 1024 + kc);
            int d = tid >> 3, seg = tid & 7;
            size_t go = (size_t)d * 2048 + seg * 16;
            uint32_t so = (uint32_t)d * 144 + seg * 16;
            CP16(sv + so, gvh + go);
        }
        CP_COMMIT();
    };

    issueKV(0, 0);

    float o[4][4];
    float m[2], l[2];
#pragma unroll
    for (int b = 0; b < 4; b++)
#pragma unroll
        for (int q = 0; q < 4; q++) o[b][q] = 0.0f;
    m[0] = m[1] = -1e30f; l[0] = l[1] = 0.0f;

    uint32_t qfh[2][4], qfl[2][4];

    const int a_r = lane & 15;
    const int a_c = (lane >> 4) << 3;
    const int b_rr = (lane & 7) + ((lane >> 4) << 3);
    const int b_cc = ((lane >> 3) & 1) << 3;

    for (int c = 0; c < 16; c++) {
        const int buf = c & 1;
        if (c + 1 < 16) { issueKV(c + 1, buf ^ 1); CP_WAIT1(); }
        else            { CP_WAIT0(); }
        __syncthreads();

        if (c == 0) {
#pragma unroll
            for (int kk = 0; kk < 2; kk++) {
                uint32_t ao = (uint32_t)(warp * 16 + a_r) * 80 + (kk * 16 + a_c) * 2;
                LDSM4(qfh[kk], sb + AT_QH + ao);
                LDSM4(qfl[kk], sb + AT_QL + ao);
            }
        }

        const uint32_t sk = sb + AT_K + buf * 5120;
        const uint32_t sv = sb + AT_V + buf * 4608;

        float s[8][4];
#pragma unroll
        for (int b = 0; b < 8; b++)
#pragma unroll
            for (int q = 0; q < 4; q++) s[b][q] = 0.0f;

#pragma unroll
        for (int g = 0; g < 4; g++) {
            uint32_t kfh[2][4];
#pragma unroll
            for (int kk = 0; kk < 2; kk++) {
                uint32_t bo = (uint32_t)(g * 16 + b_rr) * 80 + (kk * 16 + b_cc) * 2;
                LDSM4(kfh[kk], sk + bo);
            }
#pragma unroll
            for (int nb = 0; nb < 2; nb++) {
                const int nt = g * 2 + nb, sl = nb << 1;
#pragma unroll
                for (int kk = 0; kk < 2; kk++) {
                    MMA_BF16(s[nt], qfh[kk], kfh[kk][sl], kfh[kk][sl + 1]);
                    MMA_BF16(s[nt], qfl[kk], kfh[kk][sl], kfh[kk][sl + 1]);
                }
            }
        }

        float alpha[2], mn2[2];
#pragma unroll
        for (int h = 0; h < 2; h++) {
            float mx = -1e30f;
#pragma unroll
            for (int nt = 0; nt < 8; nt++) {
                mx = fmaxf(mx, s[nt][2 * h]);
                mx = fmaxf(mx, s[nt][2 * h + 1]);
            }
            mx = fmaxf(mx, __shfl_xor_sync(0xffffffffu, mx, 1));
            mx = fmaxf(mx, __shfl_xor_sync(0xffffffffu, mx, 2));
            float mn = fmaxf(m[h], mx);
            alpha[h] = ex2((m[h] - mn) * BETA);
            mn2[h] = mn;
            m[h] = mn;
        }
        {
            float nm0 = mn2[0] * BETA, nm1 = mn2[1] * BETA;
#pragma unroll
            for (int nt = 0; nt < 8; nt++) {
                s[nt][0] = ex2(fmaf(s[nt][0], BETA, -nm0));
                s[nt][1] = ex2(fmaf(s[nt][1], BETA, -nm0));
                s[nt][2] = ex2(fmaf(s[nt][2], BETA, -nm1));
                s[nt][3] = ex2(fmaf(s[nt][3], BETA, -nm1));
            }
        }
#pragma unroll
        for (int h = 0; h < 2; h++) {
            float su = 0.0f;
#pragma unroll
            for (int nt = 0; nt < 8; nt++)
                su += s[nt][2 * h] + s[nt][2 * h + 1];
            su += __shfl_xor_sync(0xffffffffu, su, 1);
            su += __shfl_xor_sync(0xffffffffu, su, 2);
            l[h] = l[h] * alpha[h] + su;
        }
#pragma unroll
        for (int nb = 0; nb < 4; nb++) {
            o[nb][0] *= alpha[0];
            o[nb][1] *= alpha[0];
            o[nb][2] *= alpha[1];
            o[nb][3] *= alpha[1];
        }

#pragma unroll
        for (int kt = 0; kt < 4; kt++) {
            uint32_t vfh[2][4];
#pragma unroll
            for (int g = 0; g < 2; g++) {
                uint32_t bo = (uint32_t)(g * 16 + b_rr) * 144 + (kt * 16 + b_cc) * 2;
                LDSM4(vfh[g], sv + bo);
            }
            const int t0 = kt * 2, t1 = kt * 2 + 1;
            uint32_t ph[4], pl[4];
            split2_pack(s[t0][0], s[t0][1], ph[0], pl[0]);
            split2_pack(s[t0][2], s[t0][3], ph[1], pl[1]);
            split2_pack(s[t1][0], s[t1][1], ph[2], pl[2]);
            split2_pack(s[t1][2], s[t1][3], ph[3], pl[3]);
#pragma unroll
            for (int nb = 0; nb < 4; nb++) {
                const int g = nb >> 1, sl = (nb & 1) << 1;
                MMA_BF16(o[nb], ph, vfh[g][sl], vfh[g][sl + 1]);
                MMA_BF16(o[nb], pl, vfh[g][sl], vfh[g][sl + 1]);
            }
        }
        __syncthreads();
    }

    const int b  = bh >> 3;
    const int hh = bh & 7;
    {
        float i0 = 1.0f / l[0], i1 = 1.0f / l[1];
#pragma unroll
        for (int h = 0; h < 2; h++) {
            int row = b * 1024 + q0 + warp * 16 + h * 8 + (lane >> 2);
            float inv = h ? i1 : i0;
#pragma unroll
            for (int nb = 0; nb < 4; nb++) {
                int d = nb * 8 + ((lane & 3) << 1);
                float v0 = o[nb][2 * h]     * inv;
                float v1 = o[nb][2 * h + 1] * inv;
                uint32_t hw, lw;
                split2_pack(v0, v1, hw, lw);
                size_t a = (size_t)row * Dn + hh * 32 + d;
                *(uint32_t*)(Oh + a) = hw;
                *(uint32_t*)(Ol + a) = lw;
            }
        }
    }
}

// ---------------------------------------------------------------------------
// Gather + MCSP
// ---------------------------------------------------------------------------
__global__ __launch_bounds__(256) void gather_cls_kernel(
    const float* __restrict__ out, const float* __restrict__ qpos,
    const float* __restrict__ fgs, const int* __restrict__ il,
    const float* __restrict__ Wcls, const float* __restrict__ bcls,
    float* __restrict__ tgt,
    __nv_bfloat16* __restrict__ tgh, __nv_bfloat16* __restrict__ tgl,
    __nv_bfloat16* __restrict__ qkh, __nv_bfloat16* __restrict__ qkl)
{
    __shared__ float qs[Dn];
    __shared__ float sc[16];

    int row = blockIdx.x;
    int b   = row >> 10;
    int t   = threadIdx.x;
    int lane = t & 31, w = t >> 5;
    int idx = il[row];
    size_t src = ((size_t)b * NN + idx) * Dn + t;
    float qv = out[src];
    qs[t] = qv;
    __syncthreads();

#pragma unroll
    for (int ci = 0; ci < 2; ci++) {
        int c = w + ci * 8;
        if (c < NCLSn) {
            float sum = 0.0f;
#pragma unroll
            for (int j = 0; j < 8; j++) {
                int e = lane + (j << 5);
                sum += qs[e] * Wcls[e * NCLSn + c];
            }
#pragma unroll
            for (int o = 16; o; o >>= 1) sum += __shfl_down_sync(0xffffffffu, sum, o);
            if (lane == 0) sc[c] = sum + bcls[c];
        }
    }
    __syncthreads();

    float mx = sc[0];
#pragma unroll
    for (int c = 1; c < NCLSn; c++) mx = fmaxf(mx, sc[c]);
    float mc = (1.0f / (1.0f + __expf(-mx))) * fgs[(size_t)b * NN + idx];

    float tv = tgt[(size_t)row * Dn + t] = qv * mc;
    float qk = tv + qpos[src];
    size_t i = (size_t)row * Dn + t;
    __nv_bfloat16 h, lo;
    split_bf16(tv, h, lo); tgh[i] = h; tgl[i] = lo;
    split_bf16(qk, h, lo); qkh[i] = h; qkl[i] = lo;
}

// ---------------------------------------------------------------------------
// Host-side orchestration
// ---------------------------------------------------------------------------
extern "C" void kernel_launch(void* const* d_in, const int* in_sizes, int n_in,
                              void* d_out, int out_size)
{
    int qp_idx = (in_sizes[1] == 8) ? 4 : 1;

    const float* query = (const float*)d_in[0];
    const float* qpos  = (const float*)d_in[qp_idx];
    const float* fgs   = (const float*)d_in[6];
    const int*   fnum  = (const int*)d_in[7];
    const int*   inds  = (const int*)d_in[8];
    const float* Wq = (const float*)d_in[9],  *bq = (const float*)d_in[10];
    const float* Wk = (const float*)d_in[11], *bk = (const float*)d_in[12];
    const float* Wv = (const float*)d_in[13], *bv = (const float*)d_in[14];
    const float* Wo = (const float*)d_in[15], *bo = (const float*)d_in[16];
    const float* g1 = (const float*)d_in[17], *be1 = (const float*)d_in[18];
    const float* W1 = (const float*)d_in[19], *b1 = (const float*)d_in[20];
    const float* W2 = (const float*)d_in[21], *b2 = (const float*)d_in[22];
    const float* g2 = (const float*)d_in[23], *be2 = (const float*)d_in[24];
    const float* Wcls = (const float*)d_in[25], *bcls = (const float*)d_in[26];

    float* out = (float*)d_out;

    unsigned char* base = nullptr;
    cudaGetSymbolAddress((void**)&base, g_mem);
#define FP(off)  ((float*)(base + (off)))
#define BF(off)  ((__nv_bfloat16*)(base + (off)))

    float *tgt = FP(OF_TGT), *Xb = FP(OF_XB);
    __nv_bfloat16 *qkh = BF(OF_QKH), *qkl = BF(OF_QKL);
    __nv_bfloat16 *tgh = BF(OF_TGH), *tgl = BF(OF_TGL);
    __nv_bfloat16 *qh  = BF(OF_QH),  *ql  = BF(OF_QL);
    __nv_bfloat16 *kh  = BF(OF_KH);
    __nv_bfloat16 *vh  = BF(OF_VH);
    __nv_bfloat16 *ath = BF(OF_ATH), *atl = BF(OF_ATL);
    __nv_bfloat16 *xh  = BF(OF_XH),  *xl  = BF(OF_XL);
    __nv_bfloat16 *hh  = BF(OF_HH),  *hl  = BF(OF_HL);
    __nv_bfloat16 *wqh = BF(OF_WQH);
    __nv_bfloat16 *wkh = BF(OF_WKH);
    __nv_bfloat16 *wvh = BF(OF_WVH);
    __nv_bfloat16 *woh = BF(OF_WOH);
    __nv_bfloat16 *w1h = BF(OF_W1H);
    __nv_bfloat16 *w2h = BF(OF_W2H);

    cudaFuncSetAttribute(gemm2, cudaFuncAttributeMaxDynamicSharedMemorySize, G2_SMEM);
    cudaFuncSetAttribute(gemm_ln, cudaFuncAttributeMaxDynamicSharedMemorySize, GL_SMEM);
    cudaFuncSetAttribute(attn_tc, cudaFuncAttributeMaxDynamicSharedMemorySize, AT_SMEM);

    {
        WprepP wp{};
        wp.src[0] = Wq; wp.dh[0] = wqh;
        wp.src[1] = Wk; wp.dh[1] = wkh;
        wp.src[2] = Wv; wp.dh[2] = wvh;
        wp.src[3] = Wo; wp.dh[3] = woh;
        wp.src[4] = W1; wp.dh[4] = w1h;
        wp.src[5] = W2; wp.dh[5] = w2h;
        wprep_all<<<4608, 256>>>(wp);
    }

    cudaMemcpyAsync(out, query, sizeof(float) * (size_t)Bn * NN * Dn,
                    cudaMemcpyDeviceToDevice);

    for (int l = 0; l < L_LAYERS; l++) {
        const int* il = inds + (size_t)l * ROWS;
        const size_t wd = (size_t)l * Dn * Dn;
        const size_t wf = (size_t)l * Dn * FFNn;

        gather_cls_kernel<<<ROWS, 256>>>(out, qpos, fgs, il, Wcls, bcls,
                                         tgt, tgh, tgl, qkh, qkl);

        {   // QKV batched -> head layouts (Q split; K,V hi only)
            GemmP p{};
            p.Ah[0] = qkh; p.Al[0] = qkl; p.Wh[0] = wqh + wd;
            p.bias[0] = bq + l * Dn; p.Ch[0] = qh; p.Cl[0] = ql;
            p.Ah[1] = qkh; p.Al[1] = qkl; p.Wh[1] = wkh + wd;
            p.bias[1] = bk + l * Dn; p.Ch[1] = kh; p.Cl[1] = nullptr;
            p.Ah[2] = tgh; p.Al[2] = tgl; p.Wh[2] = wvh + wd;
            p.bias[2] = bv + l * Dn; p.Ch[2] = vh; p.Cl[2] = nullptr;
            gemm2<<<dim3(2, 64, 3), 128, G2_SMEM>>>(p, Dn, Dn, 3);
        }

        attn_tc<<<dim3(Bn * Hn, Kn / 128), 256, AT_SMEM>>>(qh, ql, kh, vh,
                                                           ath, atl);

        // O projection + LN1 fused (res = tgt) -> Xb, xh, xl
        gemm_ln<<<dim3(1, ROWS / 32), 256, GL_SMEM>>>(
            ath, atl, woh + wd,
            bo + l * Dn, g1 + l * Dn, be1 + l * Dn, tgt,
            Xb, xh, xl, nullptr, nullptr, nullptr, Dn, 1);

        {   // FFN1 (relu, bf16 split out)
            GemmP p{};
            p.Ah[0] = xh; p.Al[0] = xl; p.Wh[0] = w1h + wf;
            p.bias[0] = b1 + l * FFNn; p.Ch[0] = hh; p.Cl[0] = hl;
            gemm2<<<dim3(8, 64, 1), 128, G2_SMEM>>>(p, FFNn, Dn, 2);
        }

        // FFN2 + LN2 + ragged scatter fused (res = Xb) -> out
        gemm_ln<<<dim3(1, ROWS / 32), 256, GL_SMEM>>>(
            hh, hl, w2h + wf,
            b2 + l * Dn, g2 + l * Dn, be2 + l * Dn, Xb,
            nullptr, nullptr, nullptr, out, il, fnum, FFNn, 2);
    }
}

// round 12
// speedup vs baseline: 1.8217x; 1.3238x over previous
#include <cuda_runtime.h>
#include <cuda_bf16.h>
#include <cstdint>

// ---------------------------------------------------------------------------
// Focus-DETR encoder — round 12: full bf16 operands (single-term mma) in all
// matmuls; fp32 accumulate + fp32 residual/LN. Error budget ~2e-4 of 1e-3.
// ---------------------------------------------------------------------------

#define L_LAYERS 6
#define Bn 4
#define NN 23890
#define Kn 1024
#define Dn 256
#define Hn 8
#define HDn 32
#define FFNn 1024
#define NCLSn 15

#define ROWS (Bn * Kn)          // 4096
#define RD   (ROWS * Dn)        // 1048576 elements

// ---------------- scratch carving ----------------
constexpr size_t SZ_F  = (size_t)RD * 4;
constexpr size_t SZ_B  = (size_t)RD * 2;
constexpr size_t SZ_H  = (size_t)ROWS * FFNn * 2;
constexpr size_t SZ_WD = (size_t)L_LAYERS * Dn * Dn * 2;
constexpr size_t SZ_W1 = (size_t)L_LAYERS * Dn * FFNn * 2;

constexpr size_t OF_TGT = 0;
constexpr size_t OF_XB  = OF_TGT + SZ_F;
constexpr size_t OF_QKH = OF_XB  + SZ_F;
constexpr size_t OF_TGH = OF_QKH + SZ_B;
constexpr size_t OF_QH  = OF_TGH + SZ_B;
constexpr size_t OF_KH  = OF_QH  + SZ_B;
constexpr size_t OF_VH  = OF_KH  + SZ_B;
constexpr size_t OF_ATH = OF_VH  + SZ_B;
constexpr size_t OF_XH  = OF_ATH + SZ_B;
constexpr size_t OF_HH  = OF_XH  + SZ_B;
constexpr size_t OF_WQH = OF_HH  + SZ_H;
constexpr size_t OF_WKH = OF_WQH + SZ_WD;
constexpr size_t OF_WVH = OF_WKH + SZ_WD;
constexpr size_t OF_WOH = OF_WVH + SZ_WD;
constexpr size_t OF_W1H = OF_WOH + SZ_WD;
constexpr size_t OF_W2H = OF_W1H + SZ_W1;
constexpr size_t G_TOTAL = OF_W2H + SZ_W1;

__device__ __align__(1024) unsigned char g_mem[G_TOTAL];

// ============================ PTX helpers ==================================

__device__ __forceinline__ uint32_t smem_u32(const void* p) {
    uint32_t a;
    asm("{ .reg .u64 t; cvta.to.shared.u64 t, %1; cvt.u32.u64 %0, t; }"
        : "=r"(a) : "l"(p));
    return a;
}

#define CP16(sa, ga)                                                            \
    asm volatile("cp.async.ca.shared.global [%0], [%1], 16;"                    \
                 :: "r"(sa), "l"(__cvta_generic_to_global(ga)))
#define CP_COMMIT() asm volatile("cp.async.commit_group;" ::: "memory")
#define CP_WAIT0()  asm volatile("cp.async.wait_group 0;" ::: "memory")
#define CP_WAIT1()  asm volatile("cp.async.wait_group 1;" ::: "memory")

#define LDSM4(r, addr)                                                          \
    asm volatile("ldmatrix.sync.aligned.m8n8.x4.shared.b16 {%0,%1,%2,%3}, [%4];"\
        : "=r"((r)[0]), "=r"((r)[1]), "=r"((r)[2]), "=r"((r)[3]) : "r"(addr))

#define MMA_BF16(d, a, b0, b1)                                                  \
    asm volatile("mma.sync.aligned.m16n8k16.row.col.f32.bf16.bf16.f32 "         \
        "{%0,%1,%2,%3}, {%4,%5,%6,%7}, {%8,%9}, {%0,%1,%2,%3};"                 \
        : "+f"((d)[0]), "+f"((d)[1]), "+f"((d)[2]), "+f"((d)[3])                \
        : "r"((a)[0]), "r"((a)[1]), "r"((a)[2]), "r"((a)[3]), "r"(b0), "r"(b1))

__device__ __forceinline__ uint32_t bf2_u32(__nv_bfloat16 a, __nv_bfloat16 b) {
    union { __nv_bfloat162 v; uint32_t u; } cvt;
    cvt.v = __halves2bfloat162(a, b);
    return cvt.u;
}

__device__ __forceinline__ uint32_t pack2(float v0, float v1) {
    return bf2_u32(__float2bfloat16(v0), __float2bfloat16(v1));
}

__device__ __forceinline__ float ex2(float x) {
    float r;
    asm("ex2.approx.ftz.f32 %0, %1;" : "=f"(r) : "f"(x));
    return r;
}

// ================== weight prep: all weights (hi only) =====================
struct WprepP {
    const float* src[6];
    __nv_bfloat16* dh[6];
};

__global__ __launch_bounds__(256) void wprep_all(WprepP p)
{
    __shared__ float tile[32][33];
    int bid = blockIdx.x;
    int g, layer, kt, nt, Kd, N;
    if (bid < 1536) {
        g = bid / 384; int r = bid % 384;
        layer = r >> 6; int t = r & 63;
        kt = t >> 3; nt = t & 7; Kd = 256; N = 256;
    } else if (bid < 3072) {
        g = 4; int r = bid - 1536;
        layer = r >> 8; int t = r & 255;
        kt = t >> 5; nt = t & 31; Kd = 256; N = 1024;
    } else {
        g = 5; int r = bid - 3072;
        layer = r >> 8; int t = r & 255;
        kt = t >> 3; nt = t & 7; Kd = 1024; N = 256;
    }
    const int k0 = kt << 5, n0 = nt << 5;
    const int tx = threadIdx.x & 31, ty = threadIdx.x >> 5;

    const float* Wp = p.src[g] + (size_t)layer * Kd * N;
#pragma unroll
    for (int r = ty; r < 32; r += 8)
        tile[r][tx] = Wp[(size_t)(k0 + r) * N + n0 + tx];
    __syncthreads();

    __nv_bfloat16* Hp = p.dh[g] + ((size_t)layer * N + n0) * Kd + k0;
#pragma unroll
    for (int r = ty; r < 32; r += 8)
        Hp[(size_t)r * Kd + tx] = __float2bfloat16(tile[tx][r]);
}

// ===================== bf16 GEMM (single-term mma) =========================
struct GemmP {
    const __nv_bfloat16 *Ah[3], *Wh[3];
    const float* bias[3];
    __nv_bfloat16 *Ch[3];
};

#define G2_AH 0
#define G2_BH 5120
#define G2_BUF 15360
#define G2_SMEM (2 * G2_BUF)

__global__ __launch_bounds__(128) void gemm2(GemmP p, int Ncols, int Kd, int mode)
{
    extern __shared__ __align__(16) char smem[];
    const uint32_t sb = smem_u32(smem);

    const int z    = blockIdx.z;
    const __nv_bfloat16* Ah = p.Ah[z];
    const __nv_bfloat16* Wh = p.Wh[z];

    const int tid  = threadIdx.x;
    const int lane = tid & 31;
    const int wn   = tid >> 5;
    const int bm   = blockIdx.y << 6;
    const int bn   = blockIdx.x << 7;

    float acc[4][4][4];
#pragma unroll
    for (int i = 0; i < 4; i++)
#pragma unroll
        for (int j = 0; j < 4; j++)
#pragma unroll
            for (int q = 0; q < 4; q++) acc[i][j][q] = 0.0f;

    const int a_r = lane & 15;
    const int a_c = (lane >> 4) << 3;
    const int b_r = wn * 32 + (lane & 7) + ((lane >> 4) << 3);
    const int b_c = ((lane >> 3) & 1) << 3;

    const int nc = Kd >> 5;

    auto issue = [&](int c, int buf) {
        const uint32_t sa = sb + buf * G2_BUF;
        const size_t kb = (size_t)(c << 5) * 2;
#pragma unroll
        for (int i = 0; i < 2; i++) {           // A: 64 rows x 4 segs
            int s = tid + (i << 7);
            int row = s >> 2, seg = s & 3;
            size_t go = ((size_t)(bm + row) * Kd) * 2 + kb + seg * 16;
            uint32_t so = sa + row * 80 + seg * 16;
            CP16(so + G2_AH, (const char*)Ah + go);
        }
#pragma unroll
        for (int i = 0; i < 4; i++) {           // B: 128 rows x 4 segs
            int s = tid + (i << 7);
            int row = s >> 2, seg = s & 3;
            size_t go = ((size_t)(bn + row) * Kd) * 2 + kb + seg * 16;
            uint32_t so = sa + row * 80 + seg * 16;
            CP16(so + G2_BH, (const char*)Wh + go);
        }
        CP_COMMIT();
    };

    issue(0, 0);

    for (int c = 0; c < nc; c++) {
        const int buf = c & 1;
        if (c + 1 < nc) { issue(c + 1, buf ^ 1); CP_WAIT1(); }
        else           { CP_WAIT0(); }
        __syncthreads();

        const uint32_t sa = sb + buf * G2_BUF;
#pragma unroll
        for (int ks = 0; ks < 2; ks++) {
            uint32_t ah[4][4];
#pragma unroll
            for (int mb = 0; mb < 4; mb++) {
                uint32_t ao = sa + (uint32_t)(a_r + mb * 16) * 80 + (ks * 16 + a_c) * 2;
                LDSM4(ah[mb], ao + G2_AH);
            }
            uint32_t bh[2][4];
#pragma unroll
            for (int np = 0; np < 2; np++) {
                uint32_t bo = sa + (uint32_t)(b_r + np * 16) * 80 + (ks * 16 + b_c) * 2;
                LDSM4(bh[np], bo + G2_BH);
            }
#pragma unroll
            for (int mb = 0; mb < 4; mb++)
#pragma unroll
                for (int nb = 0; nb < 4; nb++) {
                    const int np = nb >> 1, sl = (nb & 1) << 1;
                    MMA_BF16(acc[mb][nb], ah[mb], bh[np][sl], bh[np][sl + 1]);
                }
        }
        __syncthreads();
    }

    const float* bias = p.bias[z];
    const int r0 = bm + (lane >> 2);
    const int c0 = bn + wn * 32 + ((lane & 3) << 1);

    if (mode == 2) {   // FFN1: relu + bf16 out
        __nv_bfloat16* Ch = p.Ch[z];
#pragma unroll
        for (int mb = 0; mb < 4; mb++)
#pragma unroll
            for (int nb = 0; nb < 4; nb++) {
                int rr = r0 + mb * 16, cc = c0 + nb * 8;
                float bb0 = bias[cc], bb1 = bias[cc + 1];
#pragma unroll
                for (int hrow = 0; hrow < 2; hrow++) {
                    int r = rr + hrow * 8;
                    float v0 = fmaxf(acc[mb][nb][2 * hrow]     + bb0, 0.0f);
                    float v1 = fmaxf(acc[mb][nb][2 * hrow + 1] + bb1, 0.0f);
                    *(uint32_t*)(Ch + (size_t)r * Ncols + cc) = pack2(v0, v1);
                }
            }
    } else {           // mode 3: attention QKV layout
        __nv_bfloat16* Ch = p.Ch[z];
#pragma unroll
        for (int mb = 0; mb < 4; mb++)
#pragma unroll
            for (int nb = 0; nb < 4; nb++) {
                int rr = r0 + mb * 16, cc = c0 + nb * 8;
                float bb0 = bias[cc], bb1 = bias[cc + 1];
                int bh = ((rr >> 10) << 3) + (cc >> 5);
                int d  = cc & 31;
#pragma unroll
                for (int hrow = 0; hrow < 2; hrow++) {
                    int r = rr + hrow * 8;
                    int q = r & 1023;
                    float v0 = acc[mb][nb][2 * hrow]     + bb0;
                    float v1 = acc[mb][nb][2 * hrow + 1] + bb1;
                    if (z < 2) {            // Q,K: [bh][q][32]
                        size_t a = ((size_t)bh * 1024 + q) * 32 + d;
                        *(uint32_t*)(Ch + a) = pack2(v0, v1);
                    } else {                // V: [bh][32][q] transposed
                        size_t a = ((size_t)bh * 32 + d) * 1024 + q;
                        Ch[a] = __float2bfloat16(v0);
                        Ch[a + 1024] = __float2bfloat16(v1);
                    }
                }
            }
    }
}

// ================= GEMM + LayerNorm fused (O-proj / FFN2) ==================
#define GL_AH 0
#define GL_BH 2560
#define GL_BUF 23040
#define GL_RED   46080
#define GL_BIAS  48128
#define GL_GAM   49152
#define GL_BET   50176
#define GL_SMEM  51200

__global__ __launch_bounds__(256) void gemm_ln(
    const __nv_bfloat16* __restrict__ Ah,
    const __nv_bfloat16* __restrict__ Wh,
    const float* __restrict__ bias, const float* __restrict__ gam,
    const float* __restrict__ bet, const float* __restrict__ res,
    float* __restrict__ Xout, __nv_bfloat16* __restrict__ Xh,
    float* __restrict__ out, const int* __restrict__ il,
    const int* __restrict__ fnum,
    int Kd, int mode)
{
    extern __shared__ __align__(16) char smem[];
    const uint32_t sb = smem_u32(smem);

    const int tid  = threadIdx.x;
    const int lane = tid & 31;
    const int w    = tid >> 5;
    const int bm   = blockIdx.y << 5;

    ((float*)(smem + GL_BIAS))[tid] = bias[tid];
    ((float*)(smem + GL_GAM))[tid]  = gam[tid];
    ((float*)(smem + GL_BET))[tid]  = bet[tid];

    float acc[2][4][4];
#pragma unroll
    for (int i = 0; i < 2; i++)
#pragma unroll
        for (int j = 0; j < 4; j++)
#pragma unroll
            for (int q = 0; q < 4; q++) acc[i][j][q] = 0.0f;

    const int a_r = lane & 15;
    const int a_c = (lane >> 4) << 3;
    const int b_rr = (lane & 7) + ((lane >> 4) << 3);
    const int b_cc = ((lane >> 3) & 1) << 3;

    const int nc = Kd >> 5;

    auto issue = [&](int c, int buf) {
        const uint32_t sa = sb + buf * GL_BUF;
        const size_t kb = (size_t)(c << 5) * 2;
        if (tid < 128) {                       // A: 32 rows x 4 segs
            int row = tid >> 2, seg = tid & 3;
            size_t go = ((size_t)(bm + row) * Kd) * 2 + kb + seg * 16;
            uint32_t so = sa + row * 80 + seg * 16;
            CP16(so + GL_AH, (const char*)Ah + go);
        }
#pragma unroll
        for (int i = 0; i < 4; i++) {          // B: 256 rows x 4 segs
            int s = tid + (i << 8);
            int row = s >> 2, seg = s & 3;
            size_t go = ((size_t)row * Kd) * 2 + kb + seg * 16;
            uint32_t so = sa + row * 80 + seg * 16;
            CP16(so + GL_BH, (const char*)Wh + go);
        }
        CP_COMMIT();
    };

    issue(0, 0);

    for (int c = 0; c < nc; c++) {
        const int buf = c & 1;
        if (c + 1 < nc) { issue(c + 1, buf ^ 1); CP_WAIT1(); }
        else           { CP_WAIT0(); }
        __syncthreads();

        const uint32_t sa = sb + buf * GL_BUF;
#pragma unroll
        for (int ks = 0; ks < 2; ks++) {
            uint32_t ah[2][4];
#pragma unroll
            for (int mb = 0; mb < 2; mb++) {
                uint32_t ao = sa + (uint32_t)(mb * 16 + a_r) * 80 + (ks * 16 + a_c) * 2;
                LDSM4(ah[mb], ao + GL_AH);
            }
            uint32_t bh[2][4];
#pragma unroll
            for (int np = 0; np < 2; np++) {
                uint32_t bo = sa + (uint32_t)(w * 32 + np * 16 + b_rr) * 80
                            + (ks * 16 + b_cc) * 2;
                LDSM4(bh[np], bo + GL_BH);
            }
#pragma unroll
            for (int mb = 0; mb < 2; mb++)
#pragma unroll
                for (int nb = 0; nb < 4; nb++) {
                    const int np = nb >> 1, sl = (nb & 1) << 1;
                    MMA_BF16(acc[mb][nb], ah[mb], bh[np][sl], bh[np][sl + 1]);
                }
        }
        __syncthreads();
    }

    const float* bias_s = (const float*)(smem + GL_BIAS);
    float2* red = (float2*)(smem + GL_RED);

#pragma unroll
    for (int mb = 0; mb < 2; mb++) {
        float sA = 0.f, qA = 0.f, sB = 0.f, qB = 0.f;
#pragma unroll
        for (int nb = 0; nb < 4; nb++) {
            int cc = w * 32 + nb * 8 + ((lane & 3) << 1);
            int rA = bm + mb * 16 + (lane >> 2);
            int rB = rA + 8;
            float2 resA = *(const float2*)(res + (size_t)rA * Dn + cc);
            float2 resB = *(const float2*)(res + (size_t)rB * Dn + cc);
            float bb0 = bias_s[cc], bb1 = bias_s[cc + 1];
            float v;
            v = acc[mb][nb][0] + bb0 + resA.x; acc[mb][nb][0] = v; sA += v; qA += v * v;
            v = acc[mb][nb][1] + bb1 + resA.y; acc[mb][nb][1] = v; sA += v; qA += v * v;
            v = acc[mb][nb][2] + bb0 + resB.x; acc[mb][nb][2] = v; sB += v; qB += v * v;
            v = acc[mb][nb][3] + bb1 + resB.y; acc[mb][nb][3] = v; sB += v; qB += v * v;
        }
        sA += __shfl_xor_sync(0xffffffffu, sA, 1); qA += __shfl_xor_sync(0xffffffffu, qA, 1);
        sA += __shfl_xor_sync(0xffffffffu, sA, 2); qA += __shfl_xor_sync(0xffffffffu, qA, 2);
        sB += __shfl_xor_sync(0xffffffffu, sB, 1); qB += __shfl_xor_sync(0xffffffffu, qB, 1);
        sB += __shfl_xor_sync(0xffffffffu, sB, 2); qB += __shfl_xor_sync(0xffffffffu, qB, 2);
        if ((lane & 3) == 0) {
            int rlA = mb * 16 + (lane >> 2);
            red[rlA * 8 + w] = make_float2(sA, qA);
            red[(rlA + 8) * 8 + w] = make_float2(sB, qB);
        }
    }
    __syncthreads();

    const float* gam_s = (const float*)(smem + GL_GAM);
    const float* bet_s = (const float*)(smem + GL_BET);
    const int b = bm >> 10;
    int fn = 0;
    if (mode == 2) fn = fnum[b];

#pragma unroll
    for (int mb = 0; mb < 2; mb++) {
#pragma unroll
        for (int hrow = 0; hrow < 2; hrow++) {
            int rl = mb * 16 + hrow * 8 + (lane >> 2);
            int row = bm + rl;
            float su = 0.f, sq = 0.f;
#pragma unroll
            for (int w2 = 0; w2 < 8; w2++) {
                float2 r2 = red[rl * 8 + w2];
                su += r2.x; sq += r2.y;
            }
            float mu = su * (1.0f / Dn);
            float var = sq * (1.0f / Dn) - mu * mu;
            float rs = rsqrtf(var + 1e-5f);

            if (mode == 1) {
#pragma unroll
                for (int nb = 0; nb < 4; nb++) {
                    int cc = w * 32 + nb * 8 + ((lane & 3) << 1);
                    float y0 = (acc[mb][nb][2 * hrow]     - mu) * rs * gam_s[cc]     + bet_s[cc];
                    float y1 = (acc[mb][nb][2 * hrow + 1] - mu) * rs * gam_s[cc + 1] + bet_s[cc + 1];
                    size_t a = (size_t)row * Dn + cc;
                    *(float2*)(Xout + a) = make_float2(y0, y1);
                    *(uint32_t*)(Xh + a) = pack2(y0, y1);
                }
            } else {
                int j = row & 1023;
                if (j < fn) {
                    int idx = il[row];
                    float* op = out + ((size_t)b * NN + idx) * Dn;
#pragma unroll
                    for (int nb = 0; nb < 4; nb++) {
                        int cc = w * 32 + nb * 8 + ((lane & 3) << 1);
                        float y0 = (acc[mb][nb][2 * hrow]     - mu) * rs * gam_s[cc]     + bet_s[cc];
                        float y1 = (acc[mb][nb][2 * hrow + 1] - mu) * rs * gam_s[cc + 1] + bet_s[cc + 1];
                        *(float2*)(op + cc) = make_float2(y0, y1);
                    }
                }
            }
        }
    }
}

// ====================== tensor-core flash attention ========================
// 256 threads, 8 warps x 16 q-rows, 64-key chunks, all bf16 single-term.
#define AT_QH 0
#define AT_K  10240             // + buf*5120 : Kh
#define AT_V  20480             // + buf*4608 : Vh
#define AT_SMEM 29696
#define BETA 0.2550165213f      // log2(e)/sqrt(32)

__global__ __launch_bounds__(256, 2) void attn_tc(
    const __nv_bfloat16* __restrict__ Qh,
    const __nv_bfloat16* __restrict__ Kh, const __nv_bfloat16* __restrict__ Vh,
    __nv_bfloat16* __restrict__ Oh)
{
    extern __shared__ __align__(16) char smem[];
    const uint32_t sb = smem_u32(smem);

    const int tid  = threadIdx.x;
    const int lane = tid & 31;
    const int warp = tid >> 5;
    const int bh   = blockIdx.x;
    const int q0   = blockIdx.y << 7;

    {
        const char* gqh = (const char*)(Qh + ((size_t)bh * 1024 + q0) * 32);
        int row = tid >> 1, seg = tid & 1;      // 128 rows x 4 segs = 512 ops
#pragma unroll
        for (int i = 0; i < 2; i++) {
            int s2 = seg * 2 + i;
            size_t go = (size_t)row * 64 + s2 * 16;
            uint32_t so = (uint32_t)row * 80 + s2 * 16;
            CP16(sb + AT_QH + so, gqh + go);
        }
    }

    auto issueKV = [&](int c, int buf) {
        const int kc = c << 6;
        const uint32_t sk = sb + AT_K + buf * 5120;
        const uint32_t sv = sb + AT_V + buf * 4608;
        {
            const char* gkh = (const char*)(Kh + ((size_t)bh * 1024 + kc) * 32);
            int row = tid >> 2, seg = tid & 3;
            size_t go = (size_t)row * 64 + seg * 16;
            uint32_t so = (uint32_t)row * 80 + seg * 16;
            CP16(sk + so, gkh + go);
        }
        {
            const char* gvh = (const char*)(Vh + (size_t)bh * 32 * 1024 + kc);
            int d = tid >> 3, seg = tid & 7;
            size_t go = (size_t)d * 2048 + seg * 16;
            uint32_t so = (uint32_t)d * 144 + seg * 16;
            CP16(sv + so, gvh + go);
        }
        CP_COMMIT();
    };

    issueKV(0, 0);

    float o[4][4];
    float m[2], l[2];
#pragma unroll
    for (int b = 0; b < 4; b++)
#pragma unroll
        for (int q = 0; q < 4; q++) o[b][q] = 0.0f;
    m[0] = m[1] = -1e30f; l[0] = l[1] = 0.0f;

    uint32_t qfh[2][4];

    const int a_r = lane & 15;
    const int a_c = (lane >> 4) << 3;
    const int b_rr = (lane & 7) + ((lane >> 4) << 3);
    const int b_cc = ((lane >> 3) & 1) << 3;

    for (int c = 0; c < 16; c++) {
        const int buf = c & 1;
        if (c + 1 < 16) { issueKV(c + 1, buf ^ 1); CP_WAIT1(); }
        else            { CP_WAIT0(); }
        __syncthreads();

        if (c == 0) {
#pragma unroll
            for (int kk = 0; kk < 2; kk++) {
                uint32_t ao = (uint32_t)(warp * 16 + a_r) * 80 + (kk * 16 + a_c) * 2;
                LDSM4(qfh[kk], sb + AT_QH + ao);
            }
        }

        const uint32_t sk = sb + AT_K + buf * 5120;
        const uint32_t sv = sb + AT_V + buf * 4608;

        float s[8][4];
#pragma unroll
        for (int b = 0; b < 8; b++)
#pragma unroll
            for (int q = 0; q < 4; q++) s[b][q] = 0.0f;

#pragma unroll
        for (int g = 0; g < 4; g++) {
            uint32_t kfh[2][4];
#pragma unroll
            for (int kk = 0; kk < 2; kk++) {
                uint32_t bo = (uint32_t)(g * 16 + b_rr) * 80 + (kk * 16 + b_cc) * 2;
                LDSM4(kfh[kk], sk + bo);
            }
#pragma unroll
            for (int nb = 0; nb < 2; nb++) {
                const int nt = g * 2 + nb, sl = nb << 1;
#pragma unroll
                for (int kk = 0; kk < 2; kk++)
                    MMA_BF16(s[nt], qfh[kk], kfh[kk][sl], kfh[kk][sl + 1]);
            }
        }

        float alpha[2], mn2[2];
#pragma unroll
        for (int h = 0; h < 2; h++) {
            float mx = -1e30f;
#pragma unroll
            for (int nt = 0; nt < 8; nt++) {
                mx = fmaxf(mx, s[nt][2 * h]);
                mx = fmaxf(mx, s[nt][2 * h + 1]);
            }
            mx = fmaxf(mx, __shfl_xor_sync(0xffffffffu, mx, 1));
            mx = fmaxf(mx, __shfl_xor_sync(0xffffffffu, mx, 2));
            float mn = fmaxf(m[h], mx);
            alpha[h] = ex2((m[h] - mn) * BETA);
            mn2[h] = mn;
            m[h] = mn;
        }
        {
            float nm0 = mn2[0] * BETA, nm1 = mn2[1] * BETA;
#pragma unroll
            for (int nt = 0; nt < 8; nt++) {
                s[nt][0] = ex2(fmaf(s[nt][0], BETA, -nm0));
                s[nt][1] = ex2(fmaf(s[nt][1], BETA, -nm0));
                s[nt][2] = ex2(fmaf(s[nt][2], BETA, -nm1));
                s[nt][3] = ex2(fmaf(s[nt][3], BETA, -nm1));
            }
        }
#pragma unroll
        for (int h = 0; h < 2; h++) {
            float su = 0.0f;
#pragma unroll
            for (int nt = 0; nt < 8; nt++)
                su += s[nt][2 * h] + s[nt][2 * h + 1];
            su += __shfl_xor_sync(0xffffffffu, su, 1);
            su += __shfl_xor_sync(0xffffffffu, su, 2);
            l[h] = l[h] * alpha[h] + su;
        }
#pragma unroll
        for (int nb = 0; nb < 4; nb++) {
            o[nb][0] *= alpha[0];
            o[nb][1] *= alpha[0];
            o[nb][2] *= alpha[1];
            o[nb][3] *= alpha[1];
        }

#pragma unroll
        for (int kt = 0; kt < 4; kt++) {
            uint32_t vfh[2][4];
#pragma unroll
            for (int g = 0; g < 2; g++) {
                uint32_t bo = (uint32_t)(g * 16 + b_rr) * 144 + (kt * 16 + b_cc) * 2;
                LDSM4(vfh[g], sv + bo);
            }
            const int t0 = kt * 2, t1 = kt * 2 + 1;
            uint32_t ph[4];
            ph[0] = pack2(s[t0][0], s[t0][1]);
            ph[1] = pack2(s[t0][2], s[t0][3]);
            ph[2] = pack2(s[t1][0], s[t1][1]);
            ph[3] = pack2(s[t1][2], s[t1][3]);
#pragma unroll
            for (int nb = 0; nb < 4; nb++) {
                const int g = nb >> 1, sl = (nb & 1) << 1;
                MMA_BF16(o[nb], ph, vfh[g][sl], vfh[g][sl + 1]);
            }
        }
        __syncthreads();
    }

    const int b  = bh >> 3;
    const int hh = bh & 7;
    {
        float i0 = 1.0f / l[0], i1 = 1.0f / l[1];
#pragma unroll
        for (int h = 0; h < 2; h++) {
            int row = b * 1024 + q0 + warp * 16 + h * 8 + (lane >> 2);
            float inv = h ? i1 : i0;
#pragma unroll
            for (int nb = 0; nb < 4; nb++) {
                int d = nb * 8 + ((lane & 3) << 1);
                float v0 = o[nb][2 * h]     * inv;
                float v1 = o[nb][2 * h + 1] * inv;
                size_t a = (size_t)row * Dn + hh * 32 + d;
                *(uint32_t*)(Oh + a) = pack2(v0, v1);
            }
        }
    }
}

// ---------------------------------------------------------------------------
// Gather + MCSP
// ---------------------------------------------------------------------------
__global__ __launch_bounds__(256) void gather_cls_kernel(
    const float* __restrict__ out, const float* __restrict__ qpos,
    const float* __restrict__ fgs, const int* __restrict__ il,
    const float* __restrict__ Wcls, const float* __restrict__ bcls,
    float* __restrict__ tgt,
    __nv_bfloat16* __restrict__ tgh, __nv_bfloat16* __restrict__ qkh)
{
    __shared__ float qs[Dn];
    __shared__ float sc[16];

    int row = blockIdx.x;
    int b   = row >> 10;
    int t   = threadIdx.x;
    int lane = t & 31, w = t >> 5;
    int idx = il[row];
    size_t src = ((size_t)b * NN + idx) * Dn + t;
    float qv = out[src];
    qs[t] = qv;
    __syncthreads();

#pragma unroll
    for (int ci = 0; ci < 2; ci++) {
        int c = w + ci * 8;
        if (c < NCLSn) {
            float sum = 0.0f;
#pragma unroll
            for (int j = 0; j < 8; j++) {
                int e = lane + (j << 5);
                sum += qs[e] * Wcls[e * NCLSn + c];
            }
#pragma unroll
            for (int o = 16; o; o >>= 1) sum += __shfl_down_sync(0xffffffffu, sum, o);
            if (lane == 0) sc[c] = sum + bcls[c];
        }
    }
    __syncthreads();

    float mx = sc[0];
#pragma unroll
    for (int c = 1; c < NCLSn; c++) mx = fmaxf(mx, sc[c]);
    float mc = (1.0f / (1.0f + __expf(-mx))) * fgs[(size_t)b * NN + idx];

    float tv = tgt[(size_t)row * Dn + t] = qv * mc;
    float qk = tv + qpos[src];
    size_t i = (size_t)row * Dn + t;
    tgh[i] = __float2bfloat16(tv);
    qkh[i] = __float2bfloat16(qk);
}

// ---------------------------------------------------------------------------
// Host-side orchestration
// ---------------------------------------------------------------------------
extern "C" void kernel_launch(void* const* d_in, const int* in_sizes, int n_in,
                              void* d_out, int out_size)
{
    int qp_idx = (in_sizes[1] == 8) ? 4 : 1;

    const float* query = (const float*)d_in[0];
    const float* qpos  = (const float*)d_in[qp_idx];
    const float* fgs   = (const float*)d_in[6];
    const int*   fnum  = (const int*)d_in[7];
    const int*   inds  = (const int*)d_in[8];
    const float* Wq = (const float*)d_in[9],  *bq = (const float*)d_in[10];
    const float* Wk = (const float*)d_in[11], *bk = (const float*)d_in[12];
    const float* Wv = (const float*)d_in[13], *bv = (const float*)d_in[14];
    const float* Wo = (const float*)d_in[15], *bo = (const float*)d_in[16];
    const float* g1 = (const float*)d_in[17], *be1 = (const float*)d_in[18];
    const float* W1 = (const float*)d_in[19], *b1 = (const float*)d_in[20];
    const float* W2 = (const float*)d_in[21], *b2 = (const float*)d_in[22];
    const float* g2 = (const float*)d_in[23], *be2 = (const float*)d_in[24];
    const float* Wcls = (const float*)d_in[25], *bcls = (const float*)d_in[26];

    float* out = (float*)d_out;

    unsigned char* base = nullptr;
    cudaGetSymbolAddress((void**)&base, g_mem);
#define FP(off)  ((float*)(base + (off)))
#define BF(off)  ((__nv_bfloat16*)(base + (off)))

    float *tgt = FP(OF_TGT), *Xb = FP(OF_XB);
    __nv_bfloat16 *qkh = BF(OF_QKH);
    __nv_bfloat16 *tgh = BF(OF_TGH);
    __nv_bfloat16 *qh  = BF(OF_QH);
    __nv_bfloat16 *kh  = BF(OF_KH);
    __nv_bfloat16 *vh  = BF(OF_VH);
    __nv_bfloat16 *ath = BF(OF_ATH);
    __nv_bfloat16 *xh  = BF(OF_XH);
    __nv_bfloat16 *hh  = BF(OF_HH);
    __nv_bfloat16 *wqh = BF(OF_WQH);
    __nv_bfloat16 *wkh = BF(OF_WKH);
    __nv_bfloat16 *wvh = BF(OF_WVH);
    __nv_bfloat16 *woh = BF(OF_WOH);
    __nv_bfloat16 *w1h = BF(OF_W1H);
    __nv_bfloat16 *w2h = BF(OF_W2H);

    cudaFuncSetAttribute(gemm2, cudaFuncAttributeMaxDynamicSharedMemorySize, G2_SMEM);
    cudaFuncSetAttribute(gemm_ln, cudaFuncAttributeMaxDynamicSharedMemorySize, GL_SMEM);
    cudaFuncSetAttribute(attn_tc, cudaFuncAttributeMaxDynamicSharedMemorySize, AT_SMEM);

    {
        WprepP wp{};
        wp.src[0] = Wq; wp.dh[0] = wqh;
        wp.src[1] = Wk; wp.dh[1] = wkh;
        wp.src[2] = Wv; wp.dh[2] = wvh;
        wp.src[3] = Wo; wp.dh[3] = woh;
        wp.src[4] = W1; wp.dh[4] = w1h;
        wp.src[5] = W2; wp.dh[5] = w2h;
        wprep_all<<<4608, 256>>>(wp);
    }

    cudaMemcpyAsync(out, query, sizeof(float) * (size_t)Bn * NN * Dn,
                    cudaMemcpyDeviceToDevice);

    for (int l = 0; l < L_LAYERS; l++) {
        const int* il = inds + (size_t)l * ROWS;
        const size_t wd = (size_t)l * Dn * Dn;
        const size_t wf = (size_t)l * Dn * FFNn;

        gather_cls_kernel<<<ROWS, 256>>>(out, qpos, fgs, il, Wcls, bcls,
                                         tgt, tgh, qkh);

        {   // QKV batched -> head layouts
            GemmP p{};
            p.Ah[0] = qkh; p.Wh[0] = wqh + wd; p.bias[0] = bq + l * Dn; p.Ch[0] = qh;
            p.Ah[1] = qkh; p.Wh[1] = wkh + wd; p.bias[1] = bk + l * Dn; p.Ch[1] = kh;
            p.Ah[2] = tgh; p.Wh[2] = wvh + wd; p.bias[2] = bv + l * Dn; p.Ch[2] = vh;
            gemm2<<<dim3(2, 64, 3), 128, G2_SMEM>>>(p, Dn, Dn, 3);
        }

        attn_tc<<<dim3(Bn * Hn, Kn / 128), 256, AT_SMEM>>>(qh, kh, vh, ath);

        // O projection + LN1 fused (res = tgt) -> Xb, xh
        gemm_ln<<<dim3(1, ROWS / 32), 256, GL_SMEM>>>(
            ath, woh + wd,
            bo + l * Dn, g1 + l * Dn, be1 + l * Dn, tgt,
            Xb, xh, nullptr, nullptr, nullptr, Dn, 1);

        {   // FFN1 (relu, bf16 out)
            GemmP p{};
            p.Ah[0] = xh; p.Wh[0] = w1h + wf; p.bias[0] = b1 + l * FFNn; p.Ch[0] = hh;
            gemm2<<<dim3(8, 64, 1), 128, G2_SMEM>>>(p, FFNn, Dn, 2);
        }

        // FFN2 + LN2 + ragged scatter fused (res = Xb) -> out
        gemm_ln<<<dim3(1, ROWS / 32), 256, GL_SMEM>>>(
            hh, w2h + wf,
            b2 + l * Dn, g2 + l * Dn, be2 + l * Dn, Xb,
            nullptr, nullptr, out, il, fnum, FFNn, 2);
    }
}

// round 13
// speedup vs baseline: 1.9095x; 1.0482x over previous
#include <cuda_runtime.h>
#include <cuda_bf16.h>
#include <cstdint>

// ---------------------------------------------------------------------------
// Focus-DETR encoder — round 13: no-rescale softmax (logits structurally tiny;
// BETA folded into Q; clamp@60 as overflow insurance). Rest as round 12.
// ---------------------------------------------------------------------------

#define L_LAYERS 6
#define Bn 4
#define NN 23890
#define Kn 1024
#define Dn 256
#define Hn 8
#define HDn 32
#define FFNn 1024
#define NCLSn 15

#define ROWS (Bn * Kn)          // 4096
#define RD   (ROWS * Dn)        // 1048576 elements

// ---------------- scratch carving ----------------
constexpr size_t SZ_F  = (size_t)RD * 4;
constexpr size_t SZ_B  = (size_t)RD * 2;
constexpr size_t SZ_H  = (size_t)ROWS * FFNn * 2;
constexpr size_t SZ_WD = (size_t)L_LAYERS * Dn * Dn * 2;
constexpr size_t SZ_W1 = (size_t)L_LAYERS * Dn * FFNn * 2;

constexpr size_t OF_TGT = 0;
constexpr size_t OF_XB  = OF_TGT + SZ_F;
constexpr size_t OF_QKH = OF_XB  + SZ_F;
constexpr size_t OF_TGH = OF_QKH + SZ_B;
constexpr size_t OF_QH  = OF_TGH + SZ_B;
constexpr size_t OF_KH  = OF_QH  + SZ_B;
constexpr size_t OF_VH  = OF_KH  + SZ_B;
constexpr size_t OF_ATH = OF_VH  + SZ_B;
constexpr size_t OF_XH  = OF_ATH + SZ_B;
constexpr size_t OF_HH  = OF_XH  + SZ_B;
constexpr size_t OF_WQH = OF_HH  + SZ_H;
constexpr size_t OF_WKH = OF_WQH + SZ_WD;
constexpr size_t OF_WVH = OF_WKH + SZ_WD;
constexpr size_t OF_WOH = OF_WVH + SZ_WD;
constexpr size_t OF_W1H = OF_WOH + SZ_WD;
constexpr size_t OF_W2H = OF_W1H + SZ_W1;
constexpr size_t G_TOTAL = OF_W2H + SZ_W1;

__device__ __align__(1024) unsigned char g_mem[G_TOTAL];

#define BETA 0.2550165213f      // log2(e)/sqrt(32), folded into Q

// ============================ PTX helpers ==================================

__device__ __forceinline__ uint32_t smem_u32(const void* p) {
    uint32_t a;
    asm("{ .reg .u64 t; cvta.to.shared.u64 t, %1; cvt.u32.u64 %0, t; }"
        : "=r"(a) : "l"(p));
    return a;
}

#define CP16(sa, ga)                                                            \
    asm volatile("cp.async.ca.shared.global [%0], [%1], 16;"                    \
                 :: "r"(sa), "l"(__cvta_generic_to_global(ga)))
#define CP_COMMIT() asm volatile("cp.async.commit_group;" ::: "memory")
#define CP_WAIT0()  asm volatile("cp.async.wait_group 0;" ::: "memory")
#define CP_WAIT1()  asm volatile("cp.async.wait_group 1;" ::: "memory")

#define LDSM4(r, addr)                                                          \
    asm volatile("ldmatrix.sync.aligned.m8n8.x4.shared.b16 {%0,%1,%2,%3}, [%4];"\
        : "=r"((r)[0]), "=r"((r)[1]), "=r"((r)[2]), "=r"((r)[3]) : "r"(addr))

#define MMA_BF16(d, a, b0, b1)                                                  \
    asm volatile("mma.sync.aligned.m16n8k16.row.col.f32.bf16.bf16.f32 "         \
        "{%0,%1,%2,%3}, {%4,%5,%6,%7}, {%8,%9}, {%0,%1,%2,%3};"                 \
        : "+f"((d)[0]), "+f"((d)[1]), "+f"((d)[2]), "+f"((d)[3])                \
        : "r"((a)[0]), "r"((a)[1]), "r"((a)[2]), "r"((a)[3]), "r"(b0), "r"(b1))

__device__ __forceinline__ uint32_t bf2_u32(__nv_bfloat16 a, __nv_bfloat16 b) {
    union { __nv_bfloat162 v; uint32_t u; } cvt;
    cvt.v = __halves2bfloat162(a, b);
    return cvt.u;
}

__device__ __forceinline__ uint32_t pack2(float v0, float v1) {
    return bf2_u32(__float2bfloat16(v0), __float2bfloat16(v1));
}

__device__ __forceinline__ float ex2(float x) {
    float r;
    asm("ex2.approx.ftz.f32 %0, %1;" : "=f"(r) : "f"(x));
    return r;
}

// ================== weight prep: all weights (hi only) =====================
struct WprepP {
    const float* src[6];
    __nv_bfloat16* dh[6];
};

__global__ __launch_bounds__(256) void wprep_all(WprepP p)
{
    __shared__ float tile[32][33];
    int bid = blockIdx.x;
    int g, layer, kt, nt, Kd, N;
    if (bid < 1536) {
        g = bid / 384; int r = bid % 384;
        layer = r >> 6; int t = r & 63;
        kt = t >> 3; nt = t & 7; Kd = 256; N = 256;
    } else if (bid < 3072) {
        g = 4; int r = bid - 1536;
        layer = r >> 8; int t = r & 255;
        kt = t >> 5; nt = t & 31; Kd = 256; N = 1024;
    } else {
        g = 5; int r = bid - 3072;
        layer = r >> 8; int t = r & 255;
        kt = t >> 3; nt = t & 7; Kd = 1024; N = 256;
    }
    const int k0 = kt << 5, n0 = nt << 5;
    const int tx = threadIdx.x & 31, ty = threadIdx.x >> 5;

    const float* Wp = p.src[g] + (size_t)layer * Kd * N;
#pragma unroll
    for (int r = ty; r < 32; r += 8)
        tile[r][tx] = Wp[(size_t)(k0 + r) * N + n0 + tx];
    __syncthreads();

    __nv_bfloat16* Hp = p.dh[g] + ((size_t)layer * N + n0) * Kd + k0;
#pragma unroll
    for (int r = ty; r < 32; r += 8)
        Hp[(size_t)r * Kd + tx] = __float2bfloat16(tile[tx][r]);
}

// ===================== bf16 GEMM (single-term mma) =========================
struct GemmP {
    const __nv_bfloat16 *Ah[3], *Wh[3];
    const float* bias[3];
    __nv_bfloat16 *Ch[3];
};

#define G2_AH 0
#define G2_BH 5120
#define G2_BUF 15360
#define G2_SMEM (2 * G2_BUF)

__global__ __launch_bounds__(128) void gemm2(GemmP p, int Ncols, int Kd, int mode)
{
    extern __shared__ __align__(16) char smem[];
    const uint32_t sb = smem_u32(smem);

    const int z    = blockIdx.z;
    const __nv_bfloat16* Ah = p.Ah[z];
    const __nv_bfloat16* Wh = p.Wh[z];

    const int tid  = threadIdx.x;
    const int lane = tid & 31;
    const int wn   = tid >> 5;
    const int bm   = blockIdx.y << 6;
    const int bn   = blockIdx.x << 7;

    float acc[4][4][4];
#pragma unroll
    for (int i = 0; i < 4; i++)
#pragma unroll
        for (int j = 0; j < 4; j++)
#pragma unroll
            for (int q = 0; q < 4; q++) acc[i][j][q] = 0.0f;

    const int a_r = lane & 15;
    const int a_c = (lane >> 4) << 3;
    const int b_r = wn * 32 + (lane & 7) + ((lane >> 4) << 3);
    const int b_c = ((lane >> 3) & 1) << 3;

    const int nc = Kd >> 5;

    auto issue = [&](int c, int buf) {
        const uint32_t sa = sb + buf * G2_BUF;
        const size_t kb = (size_t)(c << 5) * 2;
#pragma unroll
        for (int i = 0; i < 2; i++) {
            int s = tid + (i << 7);
            int row = s >> 2, seg = s & 3;
            size_t go = ((size_t)(bm + row) * Kd) * 2 + kb + seg * 16;
            uint32_t so = sa + row * 80 + seg * 16;
            CP16(so + G2_AH, (const char*)Ah + go);
        }
#pragma unroll
        for (int i = 0; i < 4; i++) {
            int s = tid + (i << 7);
            int row = s >> 2, seg = s & 3;
            size_t go = ((size_t)(bn + row) * Kd) * 2 + kb + seg * 16;
            uint32_t so = sa + row * 80 + seg * 16;
            CP16(so + G2_BH, (const char*)Wh + go);
        }
        CP_COMMIT();
    };

    issue(0, 0);

    for (int c = 0; c < nc; c++) {
        const int buf = c & 1;
        if (c + 1 < nc) { issue(c + 1, buf ^ 1); CP_WAIT1(); }
        else           { CP_WAIT0(); }
        __syncthreads();

        const uint32_t sa = sb + buf * G2_BUF;
#pragma unroll
        for (int ks = 0; ks < 2; ks++) {
            uint32_t ah[4][4];
#pragma unroll
            for (int mb = 0; mb < 4; mb++) {
                uint32_t ao = sa + (uint32_t)(a_r + mb * 16) * 80 + (ks * 16 + a_c) * 2;
                LDSM4(ah[mb], ao + G2_AH);
            }
            uint32_t bh[2][4];
#pragma unroll
            for (int np = 0; np < 2; np++) {
                uint32_t bo = sa + (uint32_t)(b_r + np * 16) * 80 + (ks * 16 + b_c) * 2;
                LDSM4(bh[np], bo + G2_BH);
            }
#pragma unroll
            for (int mb = 0; mb < 4; mb++)
#pragma unroll
                for (int nb = 0; nb < 4; nb++) {
                    const int np = nb >> 1, sl = (nb & 1) << 1;
                    MMA_BF16(acc[mb][nb], ah[mb], bh[np][sl], bh[np][sl + 1]);
                }
        }
        __syncthreads();
    }

    const float* bias = p.bias[z];
    const int r0 = bm + (lane >> 2);
    const int c0 = bn + wn * 32 + ((lane & 3) << 1);

    if (mode == 2) {   // FFN1: relu + bf16 out
        __nv_bfloat16* Ch = p.Ch[z];
#pragma unroll
        for (int mb = 0; mb < 4; mb++)
#pragma unroll
            for (int nb = 0; nb < 4; nb++) {
                int rr = r0 + mb * 16, cc = c0 + nb * 8;
                float bb0 = bias[cc], bb1 = bias[cc + 1];
#pragma unroll
                for (int hrow = 0; hrow < 2; hrow++) {
                    int r = rr + hrow * 8;
                    float v0 = fmaxf(acc[mb][nb][2 * hrow]     + bb0, 0.0f);
                    float v1 = fmaxf(acc[mb][nb][2 * hrow + 1] + bb1, 0.0f);
                    *(uint32_t*)(Ch + (size_t)r * Ncols + cc) = pack2(v0, v1);
                }
            }
    } else {           // mode 3: attention QKV layout (Q pre-scaled by BETA)
        __nv_bfloat16* Ch = p.Ch[z];
        const float qscale = (z == 0) ? BETA : 1.0f;
#pragma unroll
        for (int mb = 0; mb < 4; mb++)
#pragma unroll
            for (int nb = 0; nb < 4; nb++) {
                int rr = r0 + mb * 16, cc = c0 + nb * 8;
                float bb0 = bias[cc], bb1 = bias[cc + 1];
                int bh = ((rr >> 10) << 3) + (cc >> 5);
                int d  = cc & 31;
#pragma unroll
                for (int hrow = 0; hrow < 2; hrow++) {
                    int r = rr + hrow * 8;
                    int q = r & 1023;
                    float v0 = (acc[mb][nb][2 * hrow]     + bb0) * qscale;
                    float v1 = (acc[mb][nb][2 * hrow + 1] + bb1) * qscale;
                    if (z < 2) {
                        size_t a = ((size_t)bh * 1024 + q) * 32 + d;
                        *(uint32_t*)(Ch + a) = pack2(v0, v1);
                    } else {
                        size_t a = ((size_t)bh * 32 + d) * 1024 + q;
                        Ch[a] = __float2bfloat16(v0);
                        Ch[a + 1024] = __float2bfloat16(v1);
                    }
                }
            }
    }
}

// ================= GEMM + LayerNorm fused (O-proj / FFN2) ==================
#define GL_AH 0
#define GL_BH 2560
#define GL_BUF 23040
#define GL_RED   46080
#define GL_BIAS  48128
#define GL_GAM   49152
#define GL_BET   50176
#define GL_SMEM  51200

__global__ __launch_bounds__(256) void gemm_ln(
    const __nv_bfloat16* __restrict__ Ah,
    const __nv_bfloat16* __restrict__ Wh,
    const float* __restrict__ bias, const float* __restrict__ gam,
    const float* __restrict__ bet, const float* __restrict__ res,
    float* __restrict__ Xout, __nv_bfloat16* __restrict__ Xh,
    float* __restrict__ out, const int* __restrict__ il,
    const int* __restrict__ fnum,
    int Kd, int mode)
{
    extern __shared__ __align__(16) char smem[];
    const uint32_t sb = smem_u32(smem);

    const int tid  = threadIdx.x;
    const int lane = tid & 31;
    const int w    = tid >> 5;
    const int bm   = blockIdx.y << 5;

    ((float*)(smem + GL_BIAS))[tid] = bias[tid];
    ((float*)(smem + GL_GAM))[tid]  = gam[tid];
    ((float*)(smem + GL_BET))[tid]  = bet[tid];

    float acc[2][4][4];
#pragma unroll
    for (int i = 0; i < 2; i++)
#pragma unroll
        for (int j = 0; j < 4; j++)
#pragma unroll
            for (int q = 0; q < 4; q++) acc[i][j][q] = 0.0f;

    const int a_r = lane & 15;
    const int a_c = (lane >> 4) << 3;
    const int b_rr = (lane & 7) + ((lane >> 4) << 3);
    const int b_cc = ((lane >> 3) & 1) << 3;

    const int nc = Kd >> 5;

    auto issue = [&](int c, int buf) {
        const uint32_t sa = sb + buf * GL_BUF;
        const size_t kb = (size_t)(c << 5) * 2;
        if (tid < 128) {
            int row = tid >> 2, seg = tid & 3;
            size_t go = ((size_t)(bm + row) * Kd) * 2 + kb + seg * 16;
            uint32_t so = sa + row * 80 + seg * 16;
            CP16(so + GL_AH, (const char*)Ah + go);
        }
#pragma unroll
        for (int i = 0; i < 4; i++) {
            int s = tid + (i << 8);
            int row = s >> 2, seg = s & 3;
            size_t go = ((size_t)row * Kd) * 2 + kb + seg * 16;
            uint32_t so = sa + row * 80 + seg * 16;
            CP16(so + GL_BH, (const char*)Wh + go);
        }
        CP_COMMIT();
    };

    issue(0, 0);

    for (int c = 0; c < nc; c++) {
        const int buf = c & 1;
        if (c + 1 < nc) { issue(c + 1, buf ^ 1); CP_WAIT1(); }
        else           { CP_WAIT0(); }
        __syncthreads();

        const uint32_t sa = sb + buf * GL_BUF;
#pragma unroll
        for (int ks = 0; ks < 2; ks++) {
            uint32_t ah[2][4];
#pragma unroll
            for (int mb = 0; mb < 2; mb++) {
                uint32_t ao = sa + (uint32_t)(mb * 16 + a_r) * 80 + (ks * 16 + a_c) * 2;
                LDSM4(ah[mb], ao + GL_AH);
            }
            uint32_t bh[2][4];
#pragma unroll
            for (int np = 0; np < 2; np++) {
                uint32_t bo = sa + (uint32_t)(w * 32 + np * 16 + b_rr) * 80
                            + (ks * 16 + b_cc) * 2;
                LDSM4(bh[np], bo + GL_BH);
            }
#pragma unroll
            for (int mb = 0; mb < 2; mb++)
#pragma unroll
                for (int nb = 0; nb < 4; nb++) {
                    const int np = nb >> 1, sl = (nb & 1) << 1;
                    MMA_BF16(acc[mb][nb], ah[mb], bh[np][sl], bh[np][sl + 1]);
                }
        }
        __syncthreads();
    }

    const float* bias_s = (const float*)(smem + GL_BIAS);
    float2* red = (float2*)(smem + GL_RED);

#pragma unroll
    for (int mb = 0; mb < 2; mb++) {
        float sA = 0.f, qA = 0.f, sB = 0.f, qB = 0.f;
#pragma unroll
        for (int nb = 0; nb < 4; nb++) {
            int cc = w * 32 + nb * 8 + ((lane & 3) << 1);
            int rA = bm + mb * 16 + (lane >> 2);
            int rB = rA + 8;
            float2 resA = *(const float2*)(res + (size_t)rA * Dn + cc);
            float2 resB = *(const float2*)(res + (size_t)rB * Dn + cc);
            float bb0 = bias_s[cc], bb1 = bias_s[cc + 1];
            float v;
            v = acc[mb][nb][0] + bb0 + resA.x; acc[mb][nb][0] = v; sA += v; qA += v * v;
            v = acc[mb][nb][1] + bb1 + resA.y; acc[mb][nb][1] = v; sA += v; qA += v * v;
            v = acc[mb][nb][2] + bb0 + resB.x; acc[mb][nb][2] = v; sB += v; qB += v * v;
            v = acc[mb][nb][3] + bb1 + resB.y; acc[mb][nb][3] = v; sB += v; qB += v * v;
        }
        sA += __shfl_xor_sync(0xffffffffu, sA, 1); qA += __shfl_xor_sync(0xffffffffu, qA, 1);
        sA += __shfl_xor_sync(0xffffffffu, sA, 2); qA += __shfl_xor_sync(0xffffffffu, qA, 2);
        sB += __shfl_xor_sync(0xffffffffu, sB, 1); qB += __shfl_xor_sync(0xffffffffu, qB, 1);
        sB += __shfl_xor_sync(0xffffffffu, sB, 2); qB += __shfl_xor_sync(0xffffffffu, qB, 2);
        if ((lane & 3) == 0) {
            int rlA = mb * 16 + (lane >> 2);
            red[rlA * 8 + w] = make_float2(sA, qA);
            red[(rlA + 8) * 8 + w] = make_float2(sB, qB);
        }
    }
    __syncthreads();

    const float* gam_s = (const float*)(smem + GL_GAM);
    const float* bet_s = (const float*)(smem + GL_BET);
    const int b = bm >> 10;
    int fn = 0;
    if (mode == 2) fn = fnum[b];

#pragma unroll
    for (int mb = 0; mb < 2; mb++) {
#pragma unroll
        for (int hrow = 0; hrow < 2; hrow++) {
            int rl = mb * 16 + hrow * 8 + (lane >> 2);
            int row = bm + rl;
            float su = 0.f, sq = 0.f;
#pragma unroll
            for (int w2 = 0; w2 < 8; w2++) {
                float2 r2 = red[rl * 8 + w2];
                su += r2.x; sq += r2.y;
            }
            float mu = su * (1.0f / Dn);
            float var = sq * (1.0f / Dn) - mu * mu;
            float rs = rsqrtf(var + 1e-5f);

            if (mode == 1) {
#pragma unroll
                for (int nb = 0; nb < 4; nb++) {
                    int cc = w * 32 + nb * 8 + ((lane & 3) << 1);
                    float y0 = (acc[mb][nb][2 * hrow]     - mu) * rs * gam_s[cc]     + bet_s[cc];
                    float y1 = (acc[mb][nb][2 * hrow + 1] - mu) * rs * gam_s[cc + 1] + bet_s[cc + 1];
                    size_t a = (size_t)row * Dn + cc;
                    *(float2*)(Xout + a) = make_float2(y0, y1);
                    *(uint32_t*)(Xh + a) = pack2(y0, y1);
                }
            } else {
                int j = row & 1023;
                if (j < fn) {
                    int idx = il[row];
                    float* op = out + ((size_t)b * NN + idx) * Dn;
#pragma unroll
                    for (int nb = 0; nb < 4; nb++) {
                        int cc = w * 32 + nb * 8 + ((lane & 3) << 1);
                        float y0 = (acc[mb][nb][2 * hrow]     - mu) * rs * gam_s[cc]     + bet_s[cc];
                        float y1 = (acc[mb][nb][2 * hrow + 1] - mu) * rs * gam_s[cc + 1] + bet_s[cc + 1];
                        *(float2*)(op + cc) = make_float2(y0, y1);
                    }
                }
            }
        }
    }
}

// ====================== tensor-core flash attention ========================
// 256 threads, 8 warps x 16 q-rows, 64-key chunks, no-rescale softmax
// (Q pre-scaled by BETA; P = 2^min(s,60); l accumulated, reduced once).
#define AT_QH 0
#define AT_K  10240             // + buf*5120 : Kh
#define AT_V  20480             // + buf*4608 : Vh
#define AT_SMEM 29696

__global__ __launch_bounds__(256, 2) void attn_tc(
    const __nv_bfloat16* __restrict__ Qh,
    const __nv_bfloat16* __restrict__ Kh, const __nv_bfloat16* __restrict__ Vh,
    __nv_bfloat16* __restrict__ Oh)
{
    extern __shared__ __align__(16) char smem[];
    const uint32_t sb = smem_u32(smem);

    const int tid  = threadIdx.x;
    const int lane = tid & 31;
    const int warp = tid >> 5;
    const int bh   = blockIdx.x;
    const int q0   = blockIdx.y << 7;

    {
        const char* gqh = (const char*)(Qh + ((size_t)bh * 1024 + q0) * 32);
        int row = tid >> 1, seg = tid & 1;
#pragma unroll
        for (int i = 0; i < 2; i++) {
            int s2 = seg * 2 + i;
            size_t go = (size_t)row * 64 + s2 * 16;
            uint32_t so = (uint32_t)row * 80 + s2 * 16;
            CP16(sb + AT_QH + so, gqh + go);
        }
    }

    auto issueKV = [&](int c, int buf) {
        const int kc = c << 6;
        const uint32_t sk = sb + AT_K + buf * 5120;
        const uint32_t sv = sb + AT_V + buf * 4608;
        {
            const char* gkh = (const char*)(Kh + ((size_t)bh * 1024 + kc) * 32);
            int row = tid >> 2, seg = tid & 3;
            size_t go = (size_t)row * 64 + seg * 16;
            uint32_t so = (uint32_t)row * 80 + seg * 16;
            CP16(sk + so, gkh + go);
        }
        {
            const char* gvh = (const char*)(Vh + (size_t)bh * 32 * 1024 + kc);
            int d = tid >> 3, seg = tid & 7;
            size_t go = (size_t)d * 2048 + seg * 16;
            uint32_t so = (uint32_t)d * 144 + seg * 16;
            CP16(sv + so, gvh + go);
        }
        CP_COMMIT();
    };

    issueKV(0, 0);

    float o[4][4];
    float l[2];
#pragma unroll
    for (int b = 0; b < 4; b++)
#pragma unroll
        for (int q = 0; q < 4; q++) o[b][q] = 0.0f;
    l[0] = l[1] = 0.0f;

    uint32_t qfh[2][4];

    const int a_r = lane & 15;
    const int a_c = (lane >> 4) << 3;
    const int b_rr = (lane & 7) + ((lane >> 4) << 3);
    const int b_cc = ((lane >> 3) & 1) << 3;

    for (int c = 0; c < 16; c++) {
        const int buf = c & 1;
        if (c + 1 < 16) { issueKV(c + 1, buf ^ 1); CP_WAIT1(); }
        else            { CP_WAIT0(); }
        __syncthreads();

        if (c == 0) {
#pragma unroll
            for (int kk = 0; kk < 2; kk++) {
                uint32_t ao = (uint32_t)(warp * 16 + a_r) * 80 + (kk * 16 + a_c) * 2;
                LDSM4(qfh[kk], sb + AT_QH + ao);
            }
        }

        const uint32_t sk = sb + AT_K + buf * 5120;
        const uint32_t sv = sb + AT_V + buf * 4608;

        // ---- S = Q K^T (Q already includes BETA) ----
        float s[8][4];
#pragma unroll
        for (int b = 0; b < 8; b++)
#pragma unroll
            for (int q = 0; q < 4; q++) s[b][q] = 0.0f;

#pragma unroll
        for (int g = 0; g < 4; g++) {
            uint32_t kfh[2][4];
#pragma unroll
            for (int kk = 0; kk < 2; kk++) {
                uint32_t bo = (uint32_t)(g * 16 + b_rr) * 80 + (kk * 16 + b_cc) * 2;
                LDSM4(kfh[kk], sk + bo);
            }
#pragma unroll
            for (int nb = 0; nb < 2; nb++) {
                const int nt = g * 2 + nb, sl = nb << 1;
#pragma unroll
                for (int kk = 0; kk < 2; kk++)
                    MMA_BF16(s[nt], qfh[kk], kfh[kk][sl], kfh[kk][sl + 1]);
            }
        }

        // ---- P = 2^min(s,60) ; accumulate l partials ----
#pragma unroll
        for (int nt = 0; nt < 8; nt++) {
            s[nt][0] = ex2(fminf(s[nt][0], 60.0f));
            s[nt][1] = ex2(fminf(s[nt][1], 60.0f));
            s[nt][2] = ex2(fminf(s[nt][2], 60.0f));
            s[nt][3] = ex2(fminf(s[nt][3], 60.0f));
            l[0] += s[nt][0] + s[nt][1];
            l[1] += s[nt][2] + s[nt][3];
        }

        // ---- O += P V ----
#pragma unroll
        for (int kt = 0; kt < 4; kt++) {
            uint32_t vfh[2][4];
#pragma unroll
            for (int g = 0; g < 2; g++) {
                uint32_t bo = (uint32_t)(g * 16 + b_rr) * 144 + (kt * 16 + b_cc) * 2;
                LDSM4(vfh[g], sv + bo);
            }
            const int t0 = kt * 2, t1 = kt * 2 + 1;
            uint32_t ph[4];
            ph[0] = pack2(s[t0][0], s[t0][1]);
            ph[1] = pack2(s[t0][2], s[t0][3]);
            ph[2] = pack2(s[t1][0], s[t1][1]);
            ph[3] = pack2(s[t1][2], s[t1][3]);
#pragma unroll
            for (int nb = 0; nb < 4; nb++) {
                const int g = nb >> 1, sl = (nb & 1) << 1;
                MMA_BF16(o[nb], ph, vfh[g][sl], vfh[g][sl + 1]);
            }
        }
        __syncthreads();
    }

    // ---- final l reduce (once) + normalize + store ----
    l[0] += __shfl_xor_sync(0xffffffffu, l[0], 1);
    l[0] += __shfl_xor_sync(0xffffffffu, l[0], 2);
    l[1] += __shfl_xor_sync(0xffffffffu, l[1], 1);
    l[1] += __shfl_xor_sync(0xffffffffu, l[1], 2);

    const int b  = bh >> 3;
    const int hh = bh & 7;
    {
        float i0 = 1.0f / l[0], i1 = 1.0f / l[1];
#pragma unroll
        for (int h = 0; h < 2; h++) {
            int row = b * 1024 + q0 + warp * 16 + h * 8 + (lane >> 2);
            float inv = h ? i1 : i0;
#pragma unroll
            for (int nb = 0; nb < 4; nb++) {
                int d = nb * 8 + ((lane & 3) << 1);
                float v0 = o[nb][2 * h]     * inv;
                float v1 = o[nb][2 * h + 1] * inv;
                size_t a = (size_t)row * Dn + hh * 32 + d;
                *(uint32_t*)(Oh + a) = pack2(v0, v1);
            }
        }
    }
}

// ---------------------------------------------------------------------------
// Gather + MCSP
// ---------------------------------------------------------------------------
__global__ __launch_bounds__(256) void gather_cls_kernel(
    const float* __restrict__ out, const float* __restrict__ qpos,
    const float* __restrict__ fgs, const int* __restrict__ il,
    const float* __restrict__ Wcls, const float* __restrict__ bcls,
    float* __restrict__ tgt,
    __nv_bfloat16* __restrict__ tgh, __nv_bfloat16* __restrict__ qkh)
{
    __shared__ float qs[Dn];
    __shared__ float sc[16];

    int row = blockIdx.x;
    int b   = row >> 10;
    int t   = threadIdx.x;
    int lane = t & 31, w = t >> 5;
    int idx = il[row];
    size_t src = ((size_t)b * NN + idx) * Dn + t;
    float qv = out[src];
    qs[t] = qv;
    __syncthreads();

#pragma unroll
    for (int ci = 0; ci < 2; ci++) {
        int c = w + ci * 8;
        if (c < NCLSn) {
            float sum = 0.0f;
#pragma unroll
            for (int j = 0; j < 8; j++) {
                int e = lane + (j << 5);
                sum += qs[e] * Wcls[e * NCLSn + c];
            }
#pragma unroll
            for (int o = 16; o; o >>= 1) sum += __shfl_down_sync(0xffffffffu, sum, o);
            if (lane == 0) sc[c] = sum + bcls[c];
        }
    }
    __syncthreads();

    float mx = sc[0];
#pragma unroll
    for (int c = 1; c < NCLSn; c++) mx = fmaxf(mx, sc[c]);
    float mc = (1.0f / (1.0f + __expf(-mx))) * fgs[(size_t)b * NN + idx];

    float tv = tgt[(size_t)row * Dn + t] = qv * mc;
    float qk = tv + qpos[src];
    size_t i = (size_t)row * Dn + t;
    tgh[i] = __float2bfloat16(tv);
    qkh[i] = __float2bfloat16(qk);
}

// ---------------------------------------------------------------------------
// Host-side orchestration
// ---------------------------------------------------------------------------
extern "C" void kernel_launch(void* const* d_in, const int* in_sizes, int n_in,
                              void* d_out, int out_size)
{
    int qp_idx = (in_sizes[1] == 8) ? 4 : 1;

    const float* query = (const float*)d_in[0];
    const float* qpos  = (const float*)d_in[qp_idx];
    const float* fgs   = (const float*)d_in[6];
    const int*   fnum  = (const int*)d_in[7];
    const int*   inds  = (const int*)d_in[8];
    const float* Wq = (const float*)d_in[9],  *bq = (const float*)d_in[10];
    const float* Wk = (const float*)d_in[11], *bk = (const float*)d_in[12];
    const float* Wv = (const float*)d_in[13], *bv = (const float*)d_in[14];
    const float* Wo = (const float*)d_in[15], *bo = (const float*)d_in[16];
    const float* g1 = (const float*)d_in[17], *be1 = (const float*)d_in[18];
    const float* W1 = (const float*)d_in[19], *b1 = (const float*)d_in[20];
    const float* W2 = (const float*)d_in[21], *b2 = (const float*)d_in[22];
    const float* g2 = (const float*)d_in[23], *be2 = (const float*)d_in[24];
    const float* Wcls = (const float*)d_in[25], *bcls = (const float*)d_in[26];

    float* out = (float*)d_out;

    unsigned char* base = nullptr;
    cudaGetSymbolAddress((void**)&base, g_mem);
#define FP(off)  ((float*)(base + (off)))
#define BF(off)  ((__nv_bfloat16*)(base + (off)))

    float *tgt = FP(OF_TGT), *Xb = FP(OF_XB);
    __nv_bfloat16 *qkh = BF(OF_QKH);
    __nv_bfloat16 *tgh = BF(OF_TGH);
    __nv_bfloat16 *qh  = BF(OF_QH);
    __nv_bfloat16 *kh  = BF(OF_KH);
    __nv_bfloat16 *vh  = BF(OF_VH);
    __nv_bfloat16 *ath = BF(OF_ATH);
    __nv_bfloat16 *xh  = BF(OF_XH);
    __nv_bfloat16 *hh  = BF(OF_HH);
    __nv_bfloat16 *wqh = BF(OF_WQH);
    __nv_bfloat16 *wkh = BF(OF_WKH);
    __nv_bfloat16 *wvh = BF(OF_WVH);
    __nv_bfloat16 *woh = BF(OF_WOH);
    __nv_bfloat16 *w1h = BF(OF_W1H);
    __nv_bfloat16 *w2h = BF(OF_W2H);

    cudaFuncSetAttribute(gemm2, cudaFuncAttributeMaxDynamicSharedMemorySize, G2_SMEM);
    cudaFuncSetAttribute(gemm_ln, cudaFuncAttributeMaxDynamicSharedMemorySize, GL_SMEM);
    cudaFuncSetAttribute(attn_tc, cudaFuncAttributeMaxDynamicSharedMemorySize, AT_SMEM);

    {
        WprepP wp{};
        wp.src[0] = Wq; wp.dh[0] = wqh;
        wp.src[1] = Wk; wp.dh[1] = wkh;
        wp.src[2] = Wv; wp.dh[2] = wvh;
        wp.src[3] = Wo; wp.dh[3] = woh;
        wp.src[4] = W1; wp.dh[4] = w1h;
        wp.src[5] = W2; wp.dh[5] = w2h;
        wprep_all<<<4608, 256>>>(wp);
    }

    cudaMemcpyAsync(out, query, sizeof(float) * (size_t)Bn * NN * Dn,
                    cudaMemcpyDeviceToDevice);

    for (int l = 0; l < L_LAYERS; l++) {
        const int* il = inds + (size_t)l * ROWS;
        const size_t wd = (size_t)l * Dn * Dn;
        const size_t wf = (size_t)l * Dn * FFNn;

        gather_cls_kernel<<<ROWS, 256>>>(out, qpos, fgs, il, Wcls, bcls,
                                         tgt, tgh, qkh);

        {   // QKV batched -> head layouts (Q pre-scaled by BETA)
            GemmP p{};
            p.Ah[0] = qkh; p.Wh[0] = wqh + wd; p.bias[0] = bq + l * Dn; p.Ch[0] = qh;
            p.Ah[1] = qkh; p.Wh[1] = wkh + wd; p.bias[1] = bk + l * Dn; p.Ch[1] = kh;
            p.Ah[2] = tgh; p.Wh[2] = wvh + wd; p.bias[2] = bv + l * Dn; p.Ch[2] = vh;
            gemm2<<<dim3(2, 64, 3), 128, G2_SMEM>>>(p, Dn, Dn, 3);
        }

        attn_tc<<<dim3(Bn * Hn, Kn / 128), 256, AT_SMEM>>>(qh, kh, vh, ath);

        // O projection + LN1 fused (res = tgt) -> Xb, xh
        gemm_ln<<<dim3(1, ROWS / 32), 256, GL_SMEM>>>(
            ath, woh + wd,
            bo + l * Dn, g1 + l * Dn, be1 + l * Dn, tgt,
            Xb, xh, nullptr, nullptr, nullptr, Dn, 1);

        {   // FFN1 (relu, bf16 out)
            GemmP p{};
            p.Ah[0] = xh; p.Wh[0] = w1h + wf; p.bias[0] = b1 + l * FFNn; p.Ch[0] = hh;
            gemm2<<<dim3(8, 64, 1), 128, G2_SMEM>>>(p, FFNn, Dn, 2);
        }

        // FFN2 + LN2 + ragged scatter fused (res = Xb) -> out
        gemm_ln<<<dim3(1, ROWS / 32), 256, GL_SMEM>>>(
            hh, w2h + wf,
            b2 + l * Dn, g2 + l * Dn, be2 + l * Dn, Xb,
            nullptr, nullptr, out, il, fnum, FFNn, 2);
    }
}